// round 6
// baseline (speedup 1.0000x reference)
#include <cuda_runtime.h>
#include <math.h>

#define NT   256
#define BC   64
#define XP   108   // X2 pitch: 104 dup floats + 4 pad; 108 mod 32 = 12 banks/row
#define HP   132   // H pitch: 128 dup floats + 4 pad; 132 mod 32 = 4 banks/row

typedef unsigned long long ull;

#define FMA2(d, a, b, c) \
    asm("fma.rn.f32x2 %0, %1, %2, %3;" : "=l"(d) : "l"(a), "l"(b), "l"(c))
#define ADD2(d, a, b) \
    asm("add.rn.f32x2 %0, %1, %2;" : "=l"(d) : "l"(a), "l"(b))
#define UNPACK2(lo, hi, v) \
    asm("mov.b64 {%0, %1}, %2;" : "=f"(lo), "=f"(hi) : "l"(v))

__device__ __forceinline__ float tanh_fast(float x) {
    float y;
    asm("tanh.approx.f32 %0, %1;" : "=f"(y) : "f"(x));
    return y;
}

// ---------------------------------------------------------------------------
// All sizes multiples of 4 floats -> every member 16B-aligned from smem base.
// ---------------------------------------------------------------------------
struct __align__(16) Smem {
    float X2[BC * XP];   // MLP input per row, duplicated pairs {v,v}
    float H1[BC * HP];   // hidden1, duplicated pairs
    float H2[BC * HP];   // hidden2, duplicated pairs
    float W1[52 * 64];   // [k][j], k rows 50,51 zero
    float W2[64 * 64];   // [k][j]
    float W3[64 * 8];    // [k][j]
    float b1[64], b2[64], b3[8];
};

// ---------------------------------------------------------------------------
// Grey-box CSTR+flash RHS (scaled), matches reference _fg in fp32.
// ---------------------------------------------------------------------------
__device__ __forceinline__ void fg_eval(const float* x, float u0f, float u1f,
                                        float* g) {
    const float Hr  = 0.3f * x[0] + 0.7f;
    const float CAr = 0.2f * x[1] + 0.5f;
    const float CBr = 0.2f * x[2] + 0.5f;
    const float Tr  = 5.0f * x[3] + 310.0f;
    const float Hb  = 0.3f * x[4] + 0.7f;
    const float CAb = 0.2f * x[5] + 0.5f;
    const float CBb = 0.2f * x[6] + 0.5f;
    const float Tb  = 5.0f * x[7] + 310.0f;
    const float Fu  = 0.1f  * u0f + 1.0f;
    const float Du  = 0.05f * u1f + 0.5f;

    const float den = 3.5f * CAb + 1.1f * CBb;
    const float CAd = 3.5f * CAb / den;
    const float CBd = 1.1f * CBb / den;
    const float Fr  = sqrtf(Hr);
    const float Fb  = sqrtf(Hb);
    const float k1c = 20000.0f * expf(-3000.0f / Tr);
    const float r1  = k1c * CAr;
    const float rHr = 1.0f / Hr;
    const float rHb = 1.0f / Hb;

    const float dHr  = Fu + Du - Fr;
    const float dCAr = (Fu * (1.0f - CAr) + Du * (CAd - CAr)) * rHr - r1;
    const float dCBr = (-Fu * CBr + Du * (CBd - CBr)) * rHr + r1;
    const float dTr  = (Fu * (320.0f - Tr) + Du * (310.0f - Tr)) * rHr
                     - (200.0f / 15.0f) * rHr + r1 * (10.0f / 15.0f);
    const float dHb  = Fr - Fb - Du;
    const float dCAb = (Fr * (CAr - CAb) + Du * (CAb - CAd)) * rHb;
    const float dCBb = (Fr * (CBr - CBb) + Du * (CBb - CBd)) * rHb;
    const float dTb  = Fr * (Tr - Tb) * rHb + (200.0f / 15.0f) * rHb;

    g[0] = dHr  * (1.0f / 0.3f);
    g[1] = dCAr * (1.0f / 0.2f);
    g[2] = dCBr * (1.0f / 0.2f);
    g[3] = dTr  * (1.0f / 5.0f);
    g[4] = dHb  * (1.0f / 0.3f);
    g[5] = dCAb * (1.0f / 0.2f);
    g[6] = dCBb * (1.0f / 0.2f);
    g[7] = dTb  * (1.0f / 5.0f);
}

// ---------------------------------------------------------------------------
// Dense layer + tanh. Warp tile 16 rows x 32 cols; thread tile 4 rows x 4 cols.
// Thread rows = rbase + rg + 4i (i=0..3): each act LDS.128 covers 4 consecutive
// rows -> 1 wavefront (pitches 108/132 give disjoint bank ranges).
// Weight LDS.128: 8 lanes x 16B = 128B consecutive -> 1 wavefront.
// ---------------------------------------------------------------------------
template <int KP, int LDX, int LDY>
__device__ __forceinline__ void dense_tanh(const float* __restrict__ X,
                                           const float* __restrict__ W,
                                           const float* __restrict__ bias,
                                           float* __restrict__ Y,
                                           int rbase, int rg, int j0) {
    ull acc[4][2];
    const ull b0 = *(const ull*)(bias + j0);
    const ull b1 = *(const ull*)(bias + j0 + 2);
#pragma unroll
    for (int i = 0; i < 4; i++) { acc[i][0] = b0; acc[i][1] = b1; }

    const float* x0 = X + (rbase + rg) * LDX;
    const float* wj = W + j0;
#pragma unroll 4
    for (int kp = 0; kp < KP; kp++) {
        const ulonglong2 w0 = *(const ulonglong2*)(wj + (2 * kp) * 64);
        const ulonglong2 w1 = *(const ulonglong2*)(wj + (2 * kp + 1) * 64);
#pragma unroll
        for (int i = 0; i < 4; i++) {
            const ulonglong2 xv = *(const ulonglong2*)(x0 + (4 * i) * LDX + 4 * kp);
            FMA2(acc[i][0], xv.x, w0.x, acc[i][0]);
            FMA2(acc[i][1], xv.x, w0.y, acc[i][1]);
            FMA2(acc[i][0], xv.y, w1.x, acc[i][0]);
            FMA2(acc[i][1], xv.y, w1.y, acc[i][1]);
        }
    }
    float* y0 = Y + (rbase + rg) * LDY + 2 * j0;
#pragma unroll
    for (int i = 0; i < 4; i++) {
        float f0, f1, f2, f3;
        UNPACK2(f0, f1, acc[i][0]);
        UNPACK2(f2, f3, acc[i][1]);
        const float t0 = tanh_fast(f0), t1 = tanh_fast(f1);
        const float t2 = tanh_fast(f2), t3 = tanh_fast(f3);
        float* y = y0 + (4 * i) * LDY;
        *(float4*)(y)     = make_float4(t0, t0, t1, t1);
        *(float4*)(y + 4) = make_float4(t2, t2, t3, t3);
    }
}

// ---------------------------------------------------------------------------
// Persistent kernel: CTA = 64 rows, 256 threads (8 warps), grid = B/64 = 128.
// Warp w: row block rb=w>>1 (16 rows), col half ch=w&1 (32 cols).
// ---------------------------------------------------------------------------
__global__ void __launch_bounds__(NT, 1)
cstr_flash_kernel(const float* __restrict__ useq, const float* __restrict__ xGz0,
                  const float* __restrict__ gW1, const float* __restrict__ gb1,
                  const float* __restrict__ gW2, const float* __restrict__ gb2,
                  const float* __restrict__ gW3, const float* __restrict__ gb3,
                  float* __restrict__ out, int T) {
    extern __shared__ char smem_raw[];
    Smem& S = *reinterpret_cast<Smem*>(smem_raw);

    const int tid  = threadIdx.x;
    const int lane = tid & 31;
    const int w    = tid >> 5;
    const int rb   = (w >> 1) * 16;   // row block base
    const int ch   = w & 1;           // col half
    const int rg   = lane >> 3;       // row offset 0..3
    const int cx   = lane & 7;        // col group
    const int j0   = ch * 32 + 4 * cx;

    // weights
    for (int i = tid; i < 52 * 64; i += NT) S.W1[i] = (i < 50 * 64) ? gW1[i] : 0.0f;
    for (int i = tid; i < 64 * 64; i += NT) S.W2[i] = gW2[i];
    for (int i = tid; i < 64 * 8;  i += NT) S.W3[i] = gW3[i];
    if (tid < 64) { S.b1[tid] = gb1[tid]; S.b2[tid] = gb2[tid]; }
    if (tid < 8)  { S.b3[tid] = gb3[tid]; }

    // RK4 owner mapping: lane group of 4 per row
    const int  row = tid >> 2;        // 0..63
    const int  ks  = tid & 3;
    const bool own = (ks == 0);
    const long gr  = (long)blockIdx.x * BC + row;
    float* xrow = S.X2 + row * XP;

    float xG[8], xcur[8], kacc[8], yp[32];
    float u0 = 0.f, u1 = 0.f;
#pragma unroll
    for (int c = 0; c < 8; c++) { xG[c] = 0.f; xcur[c] = 0.f; kacc[c] = 0.f; }
#pragma unroll
    for (int j = 0; j < 32; j++) yp[j] = 0.f;

    if (own) {
        const float* x0 = xGz0 + gr * 48;
#pragma unroll
        for (int c = 0; c < 8; c++) xG[c] = x0[c];
#pragma unroll
        for (int j = 0; j < 32; j++) yp[j] = x0[8 + j];
        for (int v = 0; v < 48; v += 2) {
            const float f0 = x0[v], f1 = x0[v + 1];
            *(float4*)(xrow + 2 * v) = make_float4(f0, f0, f1, f1);
        }
        u0 = useq[gr * T * 2 + 0];
        u1 = useq[gr * T * 2 + 1];
        *(float4*)(xrow + 96)  = make_float4(u0, u0, u1, u1);
        *(float4*)(xrow + 100) = make_float4(0.f, 0.f, 0.f, 0.f);
        *(float4*)(xrow + 104) = make_float4(0.f, 0.f, 0.f, 0.f);
        float* op = out + gr * T * 8;
        *(float4*)(op)     = make_float4(xG[0], xG[1], xG[2], xG[3]);
        *(float4*)(op + 4) = make_float4(xG[4], xG[5], xG[6], xG[7]);
    }
    __syncthreads();

#pragma unroll 1
    for (int t = 0; t < T; t++) {
#pragma unroll 1
        for (int s = 0; s < 4; s++) {
            dense_tanh<26, XP, HP>(S.X2, S.W1, S.b1, S.H1, rb, rg, j0);
            __syncthreads();
            dense_tanh<32, HP, HP>(S.H1, S.W2, S.b2, S.H2, rb, rg, j0);
            __syncthreads();

            // ---- layer 3: 64 -> 8; 4 lanes per row, k-slice 16 each ----
            ull c4[4];
            c4[0] = 0ull; c4[1] = 0ull; c4[2] = 0ull; c4[3] = 0ull;
            const float* h2 = S.H2 + row * HP + 32 * ks;   // dup floats of k-slice
            const float* w3 = S.W3 + (16 * ks) * 8;
#pragma unroll
            for (int q = 0; q < 8; q++) {
                const ulonglong2 xv = *(const ulonglong2*)(h2 + 4 * q);   // k0,k1 dup
                const ulonglong2 wa0 = *(const ulonglong2*)(w3 + 16 * q);      // k0 j0-3
                const ulonglong2 wb0 = *(const ulonglong2*)(w3 + 16 * q + 4);  // k0 j4-7
                const ulonglong2 wa1 = *(const ulonglong2*)(w3 + 16 * q + 8);  // k1 j0-3
                const ulonglong2 wb1 = *(const ulonglong2*)(w3 + 16 * q + 12); // k1 j4-7
                FMA2(c4[0], xv.x, wa0.x, c4[0]);
                FMA2(c4[1], xv.x, wa0.y, c4[1]);
                FMA2(c4[2], xv.x, wb0.x, c4[2]);
                FMA2(c4[3], xv.x, wb0.y, c4[3]);
                FMA2(c4[0], xv.y, wa1.x, c4[0]);
                FMA2(c4[1], xv.y, wa1.y, c4[1]);
                FMA2(c4[2], xv.y, wb1.x, c4[2]);
                FMA2(c4[3], xv.y, wb1.y, c4[3]);
            }
#pragma unroll
            for (int m = 1; m <= 2; m <<= 1) {
#pragma unroll
                for (int j = 0; j < 4; j++) {
                    const ull o = __shfl_xor_sync(0xffffffffu, c4[j], m);
                    ADD2(c4[j], c4[j], o);
                }
            }

            // ---- owner epilogue ----
            if (own) {
                float fnn[8];
                UNPACK2(fnn[0], fnn[1], c4[0]);
                UNPACK2(fnn[2], fnn[3], c4[1]);
                UNPACK2(fnn[4], fnn[5], c4[2]);
                UNPACK2(fnn[6], fnn[7], c4[3]);
#pragma unroll
                for (int c = 0; c < 8; c++) fnn[c] += S.b3[c];

                float g[8];
                fg_eval((s == 0) ? xG : xcur, u0, u1, g);
                float kv[8];
#pragma unroll
                for (int c = 0; c < 8; c++) kv[c] = g[c] + fnn[c];

                if (s == 0) {
#pragma unroll
                    for (int c = 0; c < 8; c++) {
                        kacc[c] = kv[c];
                        xcur[c] = xG[c] + 0.005f * kv[c];
                    }
                    // zi -> X2 k=8..39 (dup floats 16..79)
#pragma unroll
                    for (int m = 0; m < 4; m++) {
#pragma unroll
                        for (int c = 0; c < 8; c += 2) {
                            const float a0 = yp[8 * m + c];
                            const float a1 = yp[8 * m + c + 1];
                            const float n0 = (m < 3) ? yp[8 * (m + 1) + c]     : xG[c];
                            const float n1 = (m < 3) ? yp[8 * (m + 1) + c + 1] : xG[c + 1];
                            const float z0 = 0.5f * (a0 + n0);
                            const float z1 = 0.5f * (a1 + n1);
                            *(float4*)(xrow + 16 + 2 * (8 * m + c)) =
                                make_float4(z0, z0, z1, z1);
                        }
                    }
                } else if (s == 1) {
#pragma unroll
                    for (int c = 0; c < 8; c++) {
                        kacc[c] += 2.0f * kv[c];
                        xcur[c] = xG[c] + 0.005f * kv[c];
                    }
                } else if (s == 2) {
#pragma unroll
                    for (int c = 0; c < 8; c++) {
                        kacc[c] += 2.0f * kv[c];
                        xcur[c] = xG[c] + 0.01f * kv[c];
                    }
                    // zs = [yp[8:32], xG] -> X2 k=8..39
#pragma unroll
                    for (int q = 0; q < 32; q += 2) {
                        const float z0 = (q < 24)     ? yp[8 + q]     : xG[q - 24];
                        const float z1 = (q + 1 < 24) ? yp[8 + q + 1] : xG[q + 1 - 24];
                        *(float4*)(xrow + 16 + 2 * q) = make_float4(z0, z0, z1, z1);
                    }
                } else {
#pragma unroll
                    for (int c = 0; c < 8; c++) kacc[c] += kv[c];
                    float xnew[8];
#pragma unroll
                    for (int c = 0; c < 8; c++)
                        xnew[c] = xG[c] + (0.01f / 6.0f) * kacc[c];
                    // yp <- [yp[8:], xG_old]
#pragma unroll
                    for (int j = 0; j < 24; j++) yp[j] = yp[j + 8];
#pragma unroll
                    for (int c = 0; c < 8; c++) yp[24 + c] = xG[c];
                    // upseq shift (dup floats 80..95), append u
#pragma unroll
                    for (int q = 0; q < 6; q++) {
                        xrow[80 + 2 * q]     = xrow[84 + 2 * q];
                        xrow[80 + 2 * q + 1] = xrow[85 + 2 * q];
                    }
                    xrow[92] = u0; xrow[93] = u0; xrow[94] = u1; xrow[95] = u1;
#pragma unroll
                    for (int c = 0; c < 8; c++) xG[c] = xnew[c];
                    if (t + 1 < T) {
                        u0 = useq[(gr * T + t + 1) * 2 + 0];
                        u1 = useq[(gr * T + t + 1) * 2 + 1];
                        float* op = out + (gr * T + t + 1) * 8;
                        *(float4*)(op)     = make_float4(xG[0], xG[1], xG[2], xG[3]);
                        *(float4*)(op + 4) = make_float4(xG[4], xG[5], xG[6], xG[7]);
                    }
                    *(float4*)(xrow + 96) = make_float4(u0, u0, u1, u1);
                }
                // substep x -> X2 k=0..7 (dup floats 0..15)
                const float* xw = (s == 3) ? xG : xcur;
#pragma unroll
                for (int c = 0; c < 8; c += 2) {
                    *(float4*)(xrow + 2 * c) =
                        make_float4(xw[c], xw[c], xw[c + 1], xw[c + 1]);
                }
            }
            __syncthreads();
        }
    }
}

// ---------------------------------------------------------------------------
extern "C" void kernel_launch(void* const* d_in, const int* in_sizes, int n_in,
                              void* d_out, int out_size) {
    const float* useq = (const float*)d_in[0];
    const float* xGz0 = (const float*)d_in[1];
    const float* W1   = (const float*)d_in[2];
    const float* b1   = (const float*)d_in[3];
    const float* W2   = (const float*)d_in[4];
    const float* b2   = (const float*)d_in[5];
    const float* W3   = (const float*)d_in[6];
    const float* b3   = (const float*)d_in[7];
    float* out = (float*)d_out;

    const int B = in_sizes[1] / 48;
    const int T = in_sizes[0] / (B * 2);

    const int smem = (int)sizeof(Smem);
    cudaFuncSetAttribute(cstr_flash_kernel,
                         cudaFuncAttributeMaxDynamicSharedMemorySize, smem);
    cstr_flash_kernel<<<B / BC, NT, smem>>>(useq, xGz0, W1, b1, W2, b2, W3, b3,
                                            out, T);
}

// round 7
// speedup vs baseline: 1.0100x; 1.0100x over previous
#include <cuda_runtime.h>
#include <math.h>

#define NT   128
#define BC   32
#define XP   108   // X2 pitch: 104 dup floats + 4 pad; 108 mod 32 = 12 banks/row
#define HP   132   // H pitch: 128 dup floats + 4 pad; 132 mod 32 = 4 banks/row
#define QP   36    // yp queue pitch (4 slots x 9)

typedef unsigned long long ull;

#define FMA2(d, a, b, c) \
    asm("fma.rn.f32x2 %0, %1, %2, %3;" : "=l"(d) : "l"(a), "l"(b), "l"(c))
#define ADD2(d, a, b) \
    asm("add.rn.f32x2 %0, %1, %2;" : "=l"(d) : "l"(a), "l"(b))
#define UNPACK2(lo, hi, v) \
    asm("mov.b64 {%0, %1}, %2;" : "=f"(lo), "=f"(hi) : "l"(v))

__device__ __forceinline__ float tanh_fast(float x) {
    float y;
    asm("tanh.approx.f32 %0, %1;" : "=f"(y) : "f"(x));
    return y;
}

// ---------------------------------------------------------------------------
// All sizes multiples of 4 floats -> every member 16B-aligned from smem base.
// ---------------------------------------------------------------------------
struct __align__(16) Smem {
    float X2[BC * XP];   // MLP input per row, duplicated pairs {v,v}
    float H1[BC * HP];   // hidden1, duplicated pairs
    float H2[BC * HP];   // hidden2, duplicated pairs
    float Q[BC * QP];    // ypseq circular queue: row*QP + slot*9 + c
    float W1[52 * 64];   // [k][j], k rows 50,51 zero
    float W2[64 * 64];   // [k][j]
    float W3[64 * 8];    // [k][j]
    float b1[64], b2[64], b3[8];
};

// ---------------------------------------------------------------------------
// Grey-box CSTR+flash RHS (scaled), matches reference _fg in fp32.
// ---------------------------------------------------------------------------
__device__ __forceinline__ void fg_eval(const float* x, float u0f, float u1f,
                                        float* g) {
    const float Hr  = 0.3f * x[0] + 0.7f;
    const float CAr = 0.2f * x[1] + 0.5f;
    const float CBr = 0.2f * x[2] + 0.5f;
    const float Tr  = 5.0f * x[3] + 310.0f;
    const float Hb  = 0.3f * x[4] + 0.7f;
    const float CAb = 0.2f * x[5] + 0.5f;
    const float CBb = 0.2f * x[6] + 0.5f;
    const float Tb  = 5.0f * x[7] + 310.0f;
    const float Fu  = 0.1f  * u0f + 1.0f;
    const float Du  = 0.05f * u1f + 0.5f;

    const float den = 3.5f * CAb + 1.1f * CBb;
    const float CAd = 3.5f * CAb / den;
    const float CBd = 1.1f * CBb / den;
    const float Fr  = sqrtf(Hr);
    const float Fb  = sqrtf(Hb);
    const float k1c = 20000.0f * expf(-3000.0f / Tr);
    const float r1  = k1c * CAr;
    const float rHr = 1.0f / Hr;
    const float rHb = 1.0f / Hb;

    const float dHr  = Fu + Du - Fr;
    const float dCAr = (Fu * (1.0f - CAr) + Du * (CAd - CAr)) * rHr - r1;
    const float dCBr = (-Fu * CBr + Du * (CBd - CBr)) * rHr + r1;
    const float dTr  = (Fu * (320.0f - Tr) + Du * (310.0f - Tr)) * rHr
                     - (200.0f / 15.0f) * rHr + r1 * (10.0f / 15.0f);
    const float dHb  = Fr - Fb - Du;
    const float dCAb = (Fr * (CAr - CAb) + Du * (CAb - CAd)) * rHb;
    const float dCBb = (Fr * (CBr - CBb) + Du * (CBb - CBd)) * rHb;
    const float dTb  = Fr * (Tr - Tb) * rHb + (200.0f / 15.0f) * rHb;

    g[0] = dHr  * (1.0f / 0.3f);
    g[1] = dCAr * (1.0f / 0.2f);
    g[2] = dCBr * (1.0f / 0.2f);
    g[3] = dTr  * (1.0f / 5.0f);
    g[4] = dHb  * (1.0f / 0.3f);
    g[5] = dCAb * (1.0f / 0.2f);
    g[6] = dCBb * (1.0f / 0.2f);
    g[7] = dTb  * (1.0f / 5.0f);
}

// ---------------------------------------------------------------------------
// Dense layer + tanh. Warp tile 16 rows x 32 cols; thread tile 4 rows x 4 cols.
// Thread rows = rbase + rg + 4i: act LDS.128 covers 4 distinct rows -> 1 wf.
// Weight LDS.128: 8 lanes x 16B = 128B consecutive -> 1 wf.
// ---------------------------------------------------------------------------
template <int KP, int LDX, int LDY>
__device__ __forceinline__ void dense_tanh(const float* __restrict__ X,
                                           const float* __restrict__ W,
                                           const float* __restrict__ bias,
                                           float* __restrict__ Y,
                                           int rbase, int rg, int j0) {
    ull acc[4][2];
    const ull b0 = *(const ull*)(bias + j0);
    const ull b1 = *(const ull*)(bias + j0 + 2);
#pragma unroll
    for (int i = 0; i < 4; i++) { acc[i][0] = b0; acc[i][1] = b1; }

    const float* x0 = X + (rbase + rg) * LDX;
    const float* wj = W + j0;
#pragma unroll 4
    for (int kp = 0; kp < KP; kp++) {
        const ulonglong2 w0 = *(const ulonglong2*)(wj + (2 * kp) * 64);
        const ulonglong2 w1 = *(const ulonglong2*)(wj + (2 * kp + 1) * 64);
#pragma unroll
        for (int i = 0; i < 4; i++) {
            const ulonglong2 xv = *(const ulonglong2*)(x0 + (4 * i) * LDX + 4 * kp);
            FMA2(acc[i][0], xv.x, w0.x, acc[i][0]);
            FMA2(acc[i][1], xv.x, w0.y, acc[i][1]);
            FMA2(acc[i][0], xv.y, w1.x, acc[i][0]);
            FMA2(acc[i][1], xv.y, w1.y, acc[i][1]);
        }
    }
    float* y0 = Y + (rbase + rg) * LDY + 2 * j0;
#pragma unroll
    for (int i = 0; i < 4; i++) {
        float f0, f1, f2, f3;
        UNPACK2(f0, f1, acc[i][0]);
        UNPACK2(f2, f3, acc[i][1]);
        const float t0 = tanh_fast(f0), t1 = tanh_fast(f1);
        const float t2 = tanh_fast(f2), t3 = tanh_fast(f3);
        float* y = y0 + (4 * i) * LDY;
        *(float4*)(y)     = make_float4(t0, t0, t1, t1);
        *(float4*)(y + 4) = make_float4(t2, t2, t3, t3);
    }
}

// ---------------------------------------------------------------------------
// Persistent kernel: CTA = 32 rows, 128 threads (4 warps), 2 CTAs/SM.
// Warp w: row block rb=(w>>1)*16, col half ch=w&1.
// RK4 state: xG/xcur/kacc in regs of owner lanes; ypseq in smem circular queue.
// ---------------------------------------------------------------------------
__global__ void __launch_bounds__(NT, 2)
cstr_flash_kernel(const float* __restrict__ useq, const float* __restrict__ xGz0,
                  const float* __restrict__ gW1, const float* __restrict__ gb1,
                  const float* __restrict__ gW2, const float* __restrict__ gb2,
                  const float* __restrict__ gW3, const float* __restrict__ gb3,
                  float* __restrict__ out, int T) {
    extern __shared__ char smem_raw[];
    Smem& S = *reinterpret_cast<Smem*>(smem_raw);

    const int tid  = threadIdx.x;
    const int lane = tid & 31;
    const int w    = tid >> 5;
    const int rb   = (w >> 1) * 16;
    const int ch   = w & 1;
    const int rg   = lane >> 3;
    const int cx   = lane & 7;
    const int j0   = ch * 32 + 4 * cx;

    // weights
    for (int i = tid; i < 52 * 64; i += NT) S.W1[i] = (i < 50 * 64) ? gW1[i] : 0.0f;
    for (int i = tid; i < 64 * 64; i += NT) S.W2[i] = gW2[i];
    for (int i = tid; i < 64 * 8;  i += NT) S.W3[i] = gW3[i];
    if (tid < 64) { S.b1[tid] = gb1[tid]; S.b2[tid] = gb2[tid]; }
    if (tid < 8)  { S.b3[tid] = gb3[tid]; }

    // RK4 owner mapping: 4 lanes per row; lane ks==0 owns the row state
    const int  row = tid >> 2;        // 0..31
    const int  ks  = tid & 3;
    const bool own = (ks == 0);
    const long gr  = (long)blockIdx.x * BC + row;
    float* xrow = S.X2 + row * XP;
    float* qrow = S.Q  + row * QP;

    float xG[8], xcur[8], kacc[8];
    float u0 = 0.f, u1 = 0.f;
#pragma unroll
    for (int c = 0; c < 8; c++) { xG[c] = 0.f; xcur[c] = 0.f; kacc[c] = 0.f; }

    if (own) {
        const float* x0 = xGz0 + gr * 48;
#pragma unroll
        for (int c = 0; c < 8; c++) xG[c] = x0[c];
        // ypseq -> circular queue slots 0..3 (slot m = ypseq[m] at t=0)
#pragma unroll
        for (int m = 0; m < 4; m++)
#pragma unroll
            for (int c = 0; c < 8; c++) qrow[m * 9 + c] = x0[8 + 8 * m + c];
        for (int v = 0; v < 48; v += 2) {
            const float f0 = x0[v], f1 = x0[v + 1];
            *(float4*)(xrow + 2 * v) = make_float4(f0, f0, f1, f1);
        }
        u0 = useq[gr * T * 2 + 0];
        u1 = useq[gr * T * 2 + 1];
        *(float4*)(xrow + 96)  = make_float4(u0, u0, u1, u1);
        *(float4*)(xrow + 100) = make_float4(0.f, 0.f, 0.f, 0.f);
        *(float4*)(xrow + 104) = make_float4(0.f, 0.f, 0.f, 0.f);
        float* op = out + gr * T * 8;
        *(float4*)(op)     = make_float4(xG[0], xG[1], xG[2], xG[3]);
        *(float4*)(op + 4) = make_float4(xG[4], xG[5], xG[6], xG[7]);
    }
    __syncthreads();

#pragma unroll 1
    for (int t = 0; t < T; t++) {
#pragma unroll 1
        for (int s = 0; s < 4; s++) {
            dense_tanh<26, XP, HP>(S.X2, S.W1, S.b1, S.H1, rb, rg, j0);
            __syncthreads();
            dense_tanh<32, HP, HP>(S.H1, S.W2, S.b2, S.H2, rb, rg, j0);
            __syncthreads();

            // ---- layer 3: 64 -> 8; 4 lanes per row, k-slice 16 each ----
            ull c4[4];
            c4[0] = 0ull; c4[1] = 0ull; c4[2] = 0ull; c4[3] = 0ull;
            const float* h2 = S.H2 + row * HP + 32 * ks;
            const float* w3 = S.W3 + (16 * ks) * 8;
#pragma unroll
            for (int q = 0; q < 8; q++) {
                const ulonglong2 xv  = *(const ulonglong2*)(h2 + 4 * q);
                const ulonglong2 wa0 = *(const ulonglong2*)(w3 + 16 * q);
                const ulonglong2 wb0 = *(const ulonglong2*)(w3 + 16 * q + 4);
                const ulonglong2 wa1 = *(const ulonglong2*)(w3 + 16 * q + 8);
                const ulonglong2 wb1 = *(const ulonglong2*)(w3 + 16 * q + 12);
                FMA2(c4[0], xv.x, wa0.x, c4[0]);
                FMA2(c4[1], xv.x, wa0.y, c4[1]);
                FMA2(c4[2], xv.x, wb0.x, c4[2]);
                FMA2(c4[3], xv.x, wb0.y, c4[3]);
                FMA2(c4[0], xv.y, wa1.x, c4[0]);
                FMA2(c4[1], xv.y, wa1.y, c4[1]);
                FMA2(c4[2], xv.y, wb1.x, c4[2]);
                FMA2(c4[3], xv.y, wb1.y, c4[3]);
            }
#pragma unroll
            for (int m = 1; m <= 2; m <<= 1) {
#pragma unroll
                for (int j = 0; j < 4; j++) {
                    const ull o = __shfl_xor_sync(0xffffffffu, c4[j], m);
                    ADD2(c4[j], c4[j], o);
                }
            }

            // ---- owner epilogue ----
            if (own) {
                float fnn[8];
                UNPACK2(fnn[0], fnn[1], c4[0]);
                UNPACK2(fnn[2], fnn[3], c4[1]);
                UNPACK2(fnn[4], fnn[5], c4[2]);
                UNPACK2(fnn[6], fnn[7], c4[3]);
#pragma unroll
                for (int c = 0; c < 8; c++) fnn[c] += S.b3[c];

                float g[8];
                fg_eval((s == 0) ? xG : xcur, u0, u1, g);
                float kv[8];
#pragma unroll
                for (int c = 0; c < 8; c++) kv[c] = g[c] + fnn[c];

                if (s == 0) {
#pragma unroll
                    for (int c = 0; c < 8; c++) {
                        kacc[c] = kv[c];
                        xcur[c] = xG[c] + 0.005f * kv[c];
                    }
                    // zi (midpoints of ypseq,xG) -> X2 dup floats 16..79
#pragma unroll
                    for (int m = 0; m < 4; m++) {
                        const float* qa = qrow + ((t + m) & 3) * 9;
                        const float* qb = qrow + ((t + m + 1) & 3) * 9;
#pragma unroll
                        for (int c = 0; c < 8; c += 2) {
                            const float a0 = qa[c],     a1 = qa[c + 1];
                            const float n0 = (m < 3) ? qb[c]     : xG[c];
                            const float n1 = (m < 3) ? qb[c + 1] : xG[c + 1];
                            const float z0 = 0.5f * (a0 + n0);
                            const float z1 = 0.5f * (a1 + n1);
                            *(float4*)(xrow + 16 + 2 * (8 * m + c)) =
                                make_float4(z0, z0, z1, z1);
                        }
                    }
                } else if (s == 1) {
#pragma unroll
                    for (int c = 0; c < 8; c++) {
                        kacc[c] += 2.0f * kv[c];
                        xcur[c] = xG[c] + 0.005f * kv[c];
                    }
                } else if (s == 2) {
#pragma unroll
                    for (int c = 0; c < 8; c++) {
                        kacc[c] += 2.0f * kv[c];
                        xcur[c] = xG[c] + 0.01f * kv[c];
                    }
                    // zs = [ypseq[1:4], xG] -> X2 dup floats 16..79
#pragma unroll
                    for (int m = 0; m < 4; m++) {
                        const float* qb = qrow + ((t + m + 1) & 3) * 9;
#pragma unroll
                        for (int c = 0; c < 8; c += 2) {
                            const float z0 = (m < 3) ? qb[c]     : xG[c];
                            const float z1 = (m < 3) ? qb[c + 1] : xG[c + 1];
                            *(float4*)(xrow + 16 + 2 * (8 * m + c)) =
                                make_float4(z0, z0, z1, z1);
                        }
                    }
                } else {
#pragma unroll
                    for (int c = 0; c < 8; c++) kacc[c] += kv[c];
                    float xnew[8];
#pragma unroll
                    for (int c = 0; c < 8; c++)
                        xnew[c] = xG[c] + (0.01f / 6.0f) * kacc[c];
                    // queue: overwrite oldest slot with xG_old
                    {
                        float* qo = qrow + (t & 3) * 9;
#pragma unroll
                        for (int c = 0; c < 8; c++) qo[c] = xG[c];
                    }
                    // upseq shift (dup floats 80..95), append u
#pragma unroll
                    for (int q = 0; q < 6; q++) {
                        xrow[80 + 2 * q]     = xrow[84 + 2 * q];
                        xrow[80 + 2 * q + 1] = xrow[85 + 2 * q];
                    }
                    xrow[92] = u0; xrow[93] = u0; xrow[94] = u1; xrow[95] = u1;
#pragma unroll
                    for (int c = 0; c < 8; c++) xG[c] = xnew[c];
                    if (t + 1 < T) {
                        u0 = useq[(gr * T + t + 1) * 2 + 0];
                        u1 = useq[(gr * T + t + 1) * 2 + 1];
                        float* op = out + (gr * T + t + 1) * 8;
                        *(float4*)(op)     = make_float4(xG[0], xG[1], xG[2], xG[3]);
                        *(float4*)(op + 4) = make_float4(xG[4], xG[5], xG[6], xG[7]);
                    }
                    *(float4*)(xrow + 96) = make_float4(u0, u0, u1, u1);
                }
                // substep x -> X2 dup floats 0..15
                const float* xw = (s == 3) ? xG : xcur;
#pragma unroll
                for (int c = 0; c < 8; c += 2) {
                    *(float4*)(xrow + 2 * c) =
                        make_float4(xw[c], xw[c], xw[c + 1], xw[c + 1]);
                }
            }
            __syncthreads();
        }
    }
}

// ---------------------------------------------------------------------------
extern "C" void kernel_launch(void* const* d_in, const int* in_sizes, int n_in,
                              void* d_out, int out_size) {
    const float* useq = (const float*)d_in[0];
    const float* xGz0 = (const float*)d_in[1];
    const float* W1   = (const float*)d_in[2];
    const float* b1   = (const float*)d_in[3];
    const float* W2   = (const float*)d_in[4];
    const float* b2   = (const float*)d_in[5];
    const float* W3   = (const float*)d_in[6];
    const float* b3   = (const float*)d_in[7];
    float* out = (float*)d_out;

    const int B = in_sizes[1] / 48;
    const int T = in_sizes[0] / (B * 2);

    const int smem = (int)sizeof(Smem);
    cudaFuncSetAttribute(cstr_flash_kernel,
                         cudaFuncAttributeMaxDynamicSharedMemorySize, smem);
    cstr_flash_kernel<<<B / BC, NT, smem>>>(useq, xGz0, W1, b1, W2, b2, W3, b3,
                                            out, T);
}

// round 10
// speedup vs baseline: 1.2045x; 1.1926x over previous
#include <cuda_runtime.h>
#include <math.h>
#include <cstdint>

#define NT 128
#define BC 64
typedef unsigned long long ull;

#define FMA2(d, a, b, c) \
    asm("fma.rn.f32x2 %0, %1, %2, %3;" : "=l"(d) : "l"(a), "l"(b), "l"(c))
#define PACK2(d, lo, hi) \
    asm("mov.b64 %0, {%1, %2};" : "=l"(d) : "f"(lo), "f"(hi))
#define UNPACK2(lo, hi, v) \
    asm("mov.b64 {%0, %1}, %2;" : "=f"(lo), "=f"(hi) : "l"(v))

__device__ __forceinline__ float tanh_fast(float x) {
    float y;
    asm("tanh.approx.f32 %0, %1;" : "=f"(y) : "f"(x));
    return y;
}

// ---------------------------------------------------------------------------
// Activations TRANSPOSED: X[k][row], H[j][row] (pitch 64 rows). Weights [k][j].
// Queue pitch 33 (odd banks). All sizes multiples of 4 floats -> 16B aligned.
// ---------------------------------------------------------------------------
struct __align__(16) Smem {
    float X[52 * 64];    // MLP input, transposed [k][row], k = 0..49 used
    float H1[64 * 64];   // hidden1 transposed [j][row]
    float H2[64 * 64];   // hidden2 transposed [j][row]
    float W1[50 * 64];   // [k][j]
    float W2[64 * 64];   // [k][j]
    float W3[64 * 8];    // [k][j]
    float Q[64 * 33];    // ypseq circular queue per row
};

// ---------------------------------------------------------------------------
// Grey-box CSTR+flash RHS (scaled), fp32, matches reference _fg.
// ---------------------------------------------------------------------------
__device__ __forceinline__ void fg_eval(const float* x, float u0f, float u1f,
                                        float* g) {
    const float Hr  = 0.3f * x[0] + 0.7f;
    const float CAr = 0.2f * x[1] + 0.5f;
    const float CBr = 0.2f * x[2] + 0.5f;
    const float Tr  = 5.0f * x[3] + 310.0f;
    const float Hb  = 0.3f * x[4] + 0.7f;
    const float CAb = 0.2f * x[5] + 0.5f;
    const float CBb = 0.2f * x[6] + 0.5f;
    const float Tb  = 5.0f * x[7] + 310.0f;
    const float Fu  = 0.1f  * u0f + 1.0f;
    const float Du  = 0.05f * u1f + 0.5f;

    const float den = 3.5f * CAb + 1.1f * CBb;
    const float CAd = 3.5f * CAb / den;
    const float CBd = 1.1f * CBb / den;
    const float Fr  = sqrtf(Hr);
    const float Fb  = sqrtf(Hb);
    const float k1c = 20000.0f * expf(-3000.0f / Tr);
    const float r1  = k1c * CAr;
    const float rHr = 1.0f / Hr;
    const float rHb = 1.0f / Hb;

    g[0] = (Fu + Du - Fr) * (1.0f / 0.3f);
    g[1] = ((Fu * (1.0f - CAr) + Du * (CAd - CAr)) * rHr - r1) * (1.0f / 0.2f);
    g[2] = ((-Fu * CBr + Du * (CBd - CBr)) * rHr + r1) * (1.0f / 0.2f);
    g[3] = ((Fu * (320.0f - Tr) + Du * (310.0f - Tr)) * rHr
            - (200.0f / 15.0f) * rHr + r1 * (10.0f / 15.0f)) * (1.0f / 5.0f);
    g[4] = (Fr - Fb - Du) * (1.0f / 0.3f);
    g[5] = ((Fr * (CAr - CAb) + Du * (CAb - CAd)) * rHb) * (1.0f / 0.2f);
    g[6] = ((Fr * (CBr - CBb) + Du * (CBb - CBd)) * rHb) * (1.0f / 0.2f);
    g[7] = (Fr * (Tr - Tb) * rHb + (200.0f / 15.0f) * rHb) * (1.0f / 5.0f);
}

// ---------------------------------------------------------------------------
// Dense layer + tanh. Warp = 64 rows x 16 cols (thread = rows {2lam,2lam+1},
// cols [j0, j0+16)). Xs transposed [k][row]; Ys transposed [j][row].
// Weight loads warp-uniform broadcast (1 wf); x loads LDS.64 (2 wf).
// ---------------------------------------------------------------------------
template <int K>
__device__ __forceinline__ void dense_tanh(const float* __restrict__ Xs,
                                           const float* __restrict__ Ws,
                                           const ull* __restrict__ bb,
                                           float* __restrict__ Ys,
                                           int lam, int j0) {
    ull a0[8], a1[8];
#pragma unroll
    for (int p = 0; p < 8; p++) { a0[p] = bb[p]; a1[p] = bb[p]; }

    const float* xs = Xs + 2 * lam;
    const float* wj = Ws + j0;
#pragma unroll 2
    for (int k = 0; k < K; k++) {
        const float2 xv = *(const float2*)(xs + k * 64);
        ull xa, xb;
        PACK2(xa, xv.x, xv.x);
        PACK2(xb, xv.y, xv.y);
        const float* w = wj + k * 64;
        const ulonglong2 wA = *(const ulonglong2*)(w);
        const ulonglong2 wB = *(const ulonglong2*)(w + 4);
        const ulonglong2 wC = *(const ulonglong2*)(w + 8);
        const ulonglong2 wD = *(const ulonglong2*)(w + 12);
        FMA2(a0[0], xa, wA.x, a0[0]);  FMA2(a1[0], xb, wA.x, a1[0]);
        FMA2(a0[1], xa, wA.y, a0[1]);  FMA2(a1[1], xb, wA.y, a1[1]);
        FMA2(a0[2], xa, wB.x, a0[2]);  FMA2(a1[2], xb, wB.x, a1[2]);
        FMA2(a0[3], xa, wB.y, a0[3]);  FMA2(a1[3], xb, wB.y, a1[3]);
        FMA2(a0[4], xa, wC.x, a0[4]);  FMA2(a1[4], xb, wC.x, a1[4]);
        FMA2(a0[5], xa, wC.y, a0[5]);  FMA2(a1[5], xb, wC.y, a1[5]);
        FMA2(a0[6], xa, wD.x, a0[6]);  FMA2(a1[6], xb, wD.x, a1[6]);
        FMA2(a0[7], xa, wD.y, a0[7]);  FMA2(a1[7], xb, wD.y, a1[7]);
    }
    float* ys = Ys + 2 * lam;
#pragma unroll
    for (int p = 0; p < 8; p++) {
        float f00, f01, f10, f11;
        UNPACK2(f00, f01, a0[p]);   // row 2lam:  cols j0+2p, j0+2p+1
        UNPACK2(f10, f11, a1[p]);   // row 2lam+1
        const float t00 = tanh_fast(f00), t10 = tanh_fast(f10);
        const float t01 = tanh_fast(f01), t11 = tanh_fast(f11);
        *(float2*)(ys + (j0 + 2 * p) * 64)     = make_float2(t00, t10);
        *(float2*)(ys + (j0 + 2 * p + 1) * 64) = make_float2(t01, t11);
    }
}

// ---------------------------------------------------------------------------
// Persistent kernel: CTA = 64 rows, 128 threads; warp = col-quarter over all
// 64 rows. Owners = lanes 0..15 of each warp (row = wid*16+lam), spread over
// all 4 SMSPs for L3 + RK4 epilogue. 3 __syncthreads per substep.
// ---------------------------------------------------------------------------
__global__ void __launch_bounds__(NT, 1)
cstr_flash_kernel(const float* __restrict__ useq, const float* __restrict__ xGz0,
                  const float* __restrict__ gW1, const float* __restrict__ gb1,
                  const float* __restrict__ gW2, const float* __restrict__ gb2,
                  const float* __restrict__ gW3, const float* __restrict__ gb3,
                  float* __restrict__ out, int T) {
    extern __shared__ char smem_raw[];
    Smem& S = *reinterpret_cast<Smem*>(smem_raw);

    const int tid = threadIdx.x;
    const int wid = tid >> 5;
    const int lam = tid & 31;
    const int j0  = wid * 16;

    // weights
    for (int i = tid; i < 50 * 64; i += NT) S.W1[i] = gW1[i];
    for (int i = tid; i < 64 * 64; i += NT) S.W2[i] = gW2[i];
    for (int i = tid; i < 64 * 8;  i += NT) S.W3[i] = gW3[i];

    // bias pairs for this warp's 16 columns (registers, loaded once)
    ull bb1[8], bb2[8];
#pragma unroll
    for (int p = 0; p < 8; p++) {
        PACK2(bb1[p], gb1[j0 + 2 * p], gb1[j0 + 2 * p + 1]);
        PACK2(bb2[p], gb2[j0 + 2 * p], gb2[j0 + 2 * p + 1]);
    }

    // owner mapping: lanes 0..15 of each warp own rows wid*16 + lam
    const bool own  = (lam < 16);
    const int  rown = wid * 16 + (lam & 15);
    const long gr   = (long)blockIdx.x * BC + rown;
    float* qrow = S.Q + rown * 33;

    float xG[8], xcur[8], kacc[8], up[8], b3r[8];
    float u0 = 0.f, u1 = 0.f;
#pragma unroll
    for (int c = 0; c < 8; c++) { xG[c] = 0.f; xcur[c] = 0.f; kacc[c] = 0.f; up[c] = 0.f; b3r[c] = 0.f; }

    if (own) {
        const float* x0 = xGz0 + gr * 48;
#pragma unroll
        for (int c = 0; c < 8; c++) xG[c] = x0[c];
#pragma unroll
        for (int m = 0; m < 4; m++)
#pragma unroll
            for (int c = 0; c < 8; c++) qrow[m * 8 + c] = x0[8 + 8 * m + c];
#pragma unroll
        for (int q = 0; q < 8; q++) up[q] = x0[40 + q];
#pragma unroll
        for (int c = 0; c < 8; c++) b3r[c] = gb3[c];
        // build initial X (transposed)
#pragma unroll
        for (int c = 0; c < 8; c++)  S.X[c * 64 + rown] = x0[c];
#pragma unroll
        for (int j = 0; j < 32; j++) S.X[(8 + j) * 64 + rown] = x0[8 + j];
#pragma unroll
        for (int q = 0; q < 8; q++)  S.X[(40 + q) * 64 + rown] = x0[40 + q];
        u0 = useq[gr * T * 2 + 0];
        u1 = useq[gr * T * 2 + 1];
        S.X[48 * 64 + rown] = u0;
        S.X[49 * 64 + rown] = u1;
    }
    __syncthreads();

#pragma unroll 1
    for (int t = 0; t < T; t++) {
        if (own) {   // y_t = xG (pre-update)
            float* op = out + (gr * T + t) * 8;
            *(float4*)(op)     = make_float4(xG[0], xG[1], xG[2], xG[3]);
            *(float4*)(op + 4) = make_float4(xG[4], xG[5], xG[6], xG[7]);
        }

#pragma unroll 1
        for (int s = 0; s < 4; s++) {
            dense_tanh<50>(S.X,  S.W1, bb1, S.H1, lam, j0);
            __syncthreads();
            dense_tanh<64>(S.H1, S.W2, bb2, S.H2, lam, j0);
            __syncthreads();

            // ---- layer 3 + RK4 epilogue on owner lanes ----
            if (own) {
                ull c3[4];
                c3[0] = 0ull; c3[1] = 0ull; c3[2] = 0ull; c3[3] = 0ull;
                const float* h2 = S.H2 + rown;
#pragma unroll 4
                for (int k = 0; k < 64; k++) {
                    const float xv = h2[k * 64];
                    ull xd; PACK2(xd, xv, xv);
                    const ulonglong2 wa = *(const ulonglong2*)(S.W3 + k * 8);
                    const ulonglong2 wb = *(const ulonglong2*)(S.W3 + k * 8 + 4);
                    FMA2(c3[0], xd, wa.x, c3[0]);
                    FMA2(c3[1], xd, wa.y, c3[1]);
                    FMA2(c3[2], xd, wb.x, c3[2]);
                    FMA2(c3[3], xd, wb.y, c3[3]);
                }
                float fnn[8];
                UNPACK2(fnn[0], fnn[1], c3[0]);
                UNPACK2(fnn[2], fnn[3], c3[1]);
                UNPACK2(fnn[4], fnn[5], c3[2]);
                UNPACK2(fnn[6], fnn[7], c3[3]);
#pragma unroll
                for (int c = 0; c < 8; c++) fnn[c] += b3r[c];

                float g[8];
                fg_eval((s == 0) ? xG : xcur, u0, u1, g);
                float kv[8];
#pragma unroll
                for (int c = 0; c < 8; c++) kv[c] = g[c] + fnn[c];

                if (s == 0) {
#pragma unroll
                    for (int c = 0; c < 8; c++) {
                        kacc[c] = kv[c];
                        xcur[c] = xG[c] + 0.005f * kv[c];
                    }
                    // zi (midpoints) -> X[8..39]
#pragma unroll
                    for (int m = 0; m < 4; m++) {
                        const float* qa = qrow + ((t + m) & 3) * 8;
                        const float* qb = qrow + ((t + m + 1) & 3) * 8;
#pragma unroll
                        for (int c = 0; c < 8; c++) {
                            const float nb = (m < 3) ? qb[c] : xG[c];
                            S.X[(8 + m * 8 + c) * 64 + rown] = 0.5f * (qa[c] + nb);
                        }
                    }
                } else if (s == 1) {
#pragma unroll
                    for (int c = 0; c < 8; c++) {
                        kacc[c] += 2.0f * kv[c];
                        xcur[c] = xG[c] + 0.005f * kv[c];
                    }
                } else if (s == 2) {
#pragma unroll
                    for (int c = 0; c < 8; c++) {
                        kacc[c] += 2.0f * kv[c];
                        xcur[c] = xG[c] + 0.01f * kv[c];
                    }
                    // zs = [ypseq[1:4], xG] -> X[8..39]
#pragma unroll
                    for (int m = 0; m < 4; m++) {
                        const float* qb = qrow + ((t + m + 1) & 3) * 8;
#pragma unroll
                        for (int c = 0; c < 8; c++) {
                            const float z = (m < 3) ? qb[c] : xG[c];
                            S.X[(8 + m * 8 + c) * 64 + rown] = z;
                        }
                    }
                } else {
#pragma unroll
                    for (int c = 0; c < 8; c++) kacc[c] += kv[c];
                    float xnew[8];
#pragma unroll
                    for (int c = 0; c < 8; c++)
                        xnew[c] = xG[c] + (0.01f / 6.0f) * kacc[c];
                    // queue: oldest slot <- xG_old
                    {
                        float* qo = qrow + (t & 3) * 8;
#pragma unroll
                        for (int c = 0; c < 8; c++) qo[c] = xG[c];
                    }
                    // ypseq_{t+1} -> X[8..39]
#pragma unroll
                    for (int m = 0; m < 4; m++) {
                        const float* qn = qrow + ((t + 1 + m) & 3) * 8;
#pragma unroll
                        for (int c = 0; c < 8; c++)
                            S.X[(8 + m * 8 + c) * 64 + rown] = qn[c];
                    }
                    // upseq shift + new u
#pragma unroll
                    for (int q = 0; q < 6; q++) up[q] = up[q + 2];
                    up[6] = u0; up[7] = u1;
#pragma unroll
                    for (int q = 0; q < 8; q++)
                        S.X[(40 + q) * 64 + rown] = up[q];
                    if (t + 1 < T) {
                        u0 = useq[(gr * T + t + 1) * 2 + 0];
                        u1 = useq[(gr * T + t + 1) * 2 + 1];
                    }
                    S.X[48 * 64 + rown] = u0;
                    S.X[49 * 64 + rown] = u1;
#pragma unroll
                    for (int c = 0; c < 8; c++) xG[c] = xnew[c];
                }
                // substep x -> X[0..7]
                const float* xw = (s == 3) ? xG : xcur;
#pragma unroll
                for (int c = 0; c < 8; c++)
                    S.X[c * 64 + rown] = xw[c];
            }
            __syncthreads();
        }
    }
}

// ---------------------------------------------------------------------------
extern "C" void kernel_launch(void* const* d_in, const int* in_sizes, int n_in,
                              void* d_out, int out_size) {
    const float* useq = (const float*)d_in[0];
    const float* xGz0 = (const float*)d_in[1];
    const float* W1   = (const float*)d_in[2];
    const float* b1   = (const float*)d_in[3];
    const float* W2   = (const float*)d_in[4];
    const float* b2   = (const float*)d_in[5];
    const float* W3   = (const float*)d_in[6];
    const float* b3   = (const float*)d_in[7];
    float* out = (float*)d_out;

    const int B = in_sizes[1] / 48;
    const int T = in_sizes[0] / (B * 2);

    const int smem = (int)sizeof(Smem);
    cudaFuncSetAttribute(cstr_flash_kernel,
                         cudaFuncAttributeMaxDynamicSharedMemorySize, smem);
    cstr_flash_kernel<<<B / BC, NT, smem>>>(useq, xGz0, W1, b1, W2, b2, W3, b3,
                                            out, T);
}

// round 11
// speedup vs baseline: 1.2258x; 1.0176x over previous
#include <cuda_runtime.h>
#include <math.h>
#include <cstdint>

#define NT 256
#define BC 64
typedef unsigned long long ull;

#define FMA2(d, a, b, c) \
    asm("fma.rn.f32x2 %0, %1, %2, %3;" : "=l"(d) : "l"(a), "l"(b), "l"(c))
#define PACK2(d, lo, hi) \
    asm("mov.b64 %0, {%1, %2};" : "=l"(d) : "f"(lo), "f"(hi))
#define UNPACK2(lo, hi, v) \
    asm("mov.b64 {%0, %1}, %2;" : "=f"(lo), "=f"(hi) : "l"(v))

__device__ __forceinline__ float tanh_fast(float x) {
    float y;
    asm("tanh.approx.f32 %0, %1;" : "=f"(y) : "f"(x));
    return y;
}

// ---------------------------------------------------------------------------
// Activations TRANSPOSED: X[k][row], H[j][row] (pitch 64 rows). Weights [k][j].
// ---------------------------------------------------------------------------
struct __align__(16) Smem {
    float X[52 * 64];    // MLP input, transposed [k][row], k = 0..49 used
    float H1[64 * 64];   // hidden1 transposed [j][row]
    float H2[64 * 64];   // hidden2 transposed [j][row]
    float W1[50 * 64];   // [k][j]
    float W2[64 * 64];   // [k][j]
    float W3[64 * 8];    // [k][j]
    float Q[64 * 33];    // ypseq circular queue per row
};

// ---------------------------------------------------------------------------
// Grey-box CSTR+flash RHS (scaled), fp32, matches reference _fg.
// ---------------------------------------------------------------------------
__device__ __forceinline__ void fg_eval(const float* x, float u0f, float u1f,
                                        float* g) {
    const float Hr  = 0.3f * x[0] + 0.7f;
    const float CAr = 0.2f * x[1] + 0.5f;
    const float CBr = 0.2f * x[2] + 0.5f;
    const float Tr  = 5.0f * x[3] + 310.0f;
    const float Hb  = 0.3f * x[4] + 0.7f;
    const float CAb = 0.2f * x[5] + 0.5f;
    const float CBb = 0.2f * x[6] + 0.5f;
    const float Tb  = 5.0f * x[7] + 310.0f;
    const float Fu  = 0.1f  * u0f + 1.0f;
    const float Du  = 0.05f * u1f + 0.5f;

    const float den = 3.5f * CAb + 1.1f * CBb;
    const float CAd = 3.5f * CAb / den;
    const float CBd = 1.1f * CBb / den;
    const float Fr  = sqrtf(Hr);
    const float Fb  = sqrtf(Hb);
    const float k1c = 20000.0f * expf(-3000.0f / Tr);
    const float r1  = k1c * CAr;
    const float rHr = 1.0f / Hr;
    const float rHb = 1.0f / Hb;

    g[0] = (Fu + Du - Fr) * (1.0f / 0.3f);
    g[1] = ((Fu * (1.0f - CAr) + Du * (CAd - CAr)) * rHr - r1) * (1.0f / 0.2f);
    g[2] = ((-Fu * CBr + Du * (CBd - CBr)) * rHr + r1) * (1.0f / 0.2f);
    g[3] = ((Fu * (320.0f - Tr) + Du * (310.0f - Tr)) * rHr
            - (200.0f / 15.0f) * rHr + r1 * (10.0f / 15.0f)) * (1.0f / 5.0f);
    g[4] = (Fr - Fb - Du) * (1.0f / 0.3f);
    g[5] = ((Fr * (CAr - CAb) + Du * (CAb - CAd)) * rHb) * (1.0f / 0.2f);
    g[6] = ((Fr * (CBr - CBb) + Du * (CBb - CBd)) * rHb) * (1.0f / 0.2f);
    g[7] = (Fr * (Tr - Tb) * rHb + (200.0f / 15.0f) * rHb) * (1.0f / 5.0f);
}

// ---------------------------------------------------------------------------
// Dense layer + tanh. Warp = 64 rows x 8 cols (thread = rows {2lam,2lam+1},
// cols [j0, j0+8)). Xs transposed [k][row]; Ys transposed [j][row].
// Per k per warp: 2 uniform weight LDS.128 (1 wf each) + 1 x LDS.64 (2 wf),
// 8 FMA2 issues. 8 warps -> 2/SMSP: latency hidden, FMA+LSU jointly saturated.
// ---------------------------------------------------------------------------
template <int K>
__device__ __forceinline__ void dense_tanh(const float* __restrict__ Xs,
                                           const float* __restrict__ Ws,
                                           const ull* __restrict__ bb,
                                           float* __restrict__ Ys,
                                           int lam, int j0) {
    ull a0[4], a1[4];
#pragma unroll
    for (int p = 0; p < 4; p++) { a0[p] = bb[p]; a1[p] = bb[p]; }

    const float* xs = Xs + 2 * lam;
    const float* wj = Ws + j0;
#pragma unroll 2
    for (int k = 0; k < K; k++) {
        const float2 xv = *(const float2*)(xs + k * 64);
        ull xa, xb;
        PACK2(xa, xv.x, xv.x);
        PACK2(xb, xv.y, xv.y);
        const float* w = wj + k * 64;
        const ulonglong2 wA = *(const ulonglong2*)(w);
        const ulonglong2 wB = *(const ulonglong2*)(w + 4);
        FMA2(a0[0], xa, wA.x, a0[0]);  FMA2(a1[0], xb, wA.x, a1[0]);
        FMA2(a0[1], xa, wA.y, a0[1]);  FMA2(a1[1], xb, wA.y, a1[1]);
        FMA2(a0[2], xa, wB.x, a0[2]);  FMA2(a1[2], xb, wB.x, a1[2]);
        FMA2(a0[3], xa, wB.y, a0[3]);  FMA2(a1[3], xb, wB.y, a1[3]);
    }
    float* ys = Ys + 2 * lam;
#pragma unroll
    for (int p = 0; p < 4; p++) {
        float f00, f01, f10, f11;
        UNPACK2(f00, f01, a0[p]);   // row 2lam:  cols j0+2p, j0+2p+1
        UNPACK2(f10, f11, a1[p]);   // row 2lam+1
        const float t00 = tanh_fast(f00), t10 = tanh_fast(f10);
        const float t01 = tanh_fast(f01), t11 = tanh_fast(f11);
        *(float2*)(ys + (j0 + 2 * p) * 64)     = make_float2(t00, t10);
        *(float2*)(ys + (j0 + 2 * p + 1) * 64) = make_float2(t01, t11);
    }
}

// ---------------------------------------------------------------------------
// Persistent kernel: CTA = 64 rows, 256 threads (8 warps = 2/SMSP);
// warp = col-eighth over all 64 rows. Owners = lanes 0..7 of each warp
// (row = wid*8 + lam). 3 __syncthreads per substep.
// ---------------------------------------------------------------------------
__global__ void __launch_bounds__(NT, 1)
cstr_flash_kernel(const float* __restrict__ useq, const float* __restrict__ xGz0,
                  const float* __restrict__ gW1, const float* __restrict__ gb1,
                  const float* __restrict__ gW2, const float* __restrict__ gb2,
                  const float* __restrict__ gW3, const float* __restrict__ gb3,
                  float* __restrict__ out, int T) {
    extern __shared__ char smem_raw[];
    Smem& S = *reinterpret_cast<Smem*>(smem_raw);

    const int tid = threadIdx.x;
    const int wid = tid >> 5;
    const int lam = tid & 31;
    const int j0  = wid * 8;

    // weights
    for (int i = tid; i < 50 * 64; i += NT) S.W1[i] = gW1[i];
    for (int i = tid; i < 64 * 64; i += NT) S.W2[i] = gW2[i];
    for (int i = tid; i < 64 * 8;  i += NT) S.W3[i] = gW3[i];

    // bias pairs for this warp's 8 columns
    ull bb1[4], bb2[4];
#pragma unroll
    for (int p = 0; p < 4; p++) {
        PACK2(bb1[p], gb1[j0 + 2 * p], gb1[j0 + 2 * p + 1]);
        PACK2(bb2[p], gb2[j0 + 2 * p], gb2[j0 + 2 * p + 1]);
    }

    // owner mapping: lanes 0..7 of each warp own rows wid*8 + lam
    const bool own  = (lam < 8);
    const int  rown = wid * 8 + (lam & 7);
    const long gr   = (long)blockIdx.x * BC + rown;
    float* qrow = S.Q + rown * 33;

    float xG[8], xcur[8], kacc[8], up[8], b3r[8];
    float u0 = 0.f, u1 = 0.f;
#pragma unroll
    for (int c = 0; c < 8; c++) { xG[c] = 0.f; xcur[c] = 0.f; kacc[c] = 0.f; up[c] = 0.f; b3r[c] = 0.f; }

    if (own) {
        const float* x0 = xGz0 + gr * 48;
#pragma unroll
        for (int c = 0; c < 8; c++) xG[c] = x0[c];
#pragma unroll
        for (int m = 0; m < 4; m++)
#pragma unroll
            for (int c = 0; c < 8; c++) qrow[m * 8 + c] = x0[8 + 8 * m + c];
#pragma unroll
        for (int q = 0; q < 8; q++) up[q] = x0[40 + q];
#pragma unroll
        for (int c = 0; c < 8; c++) b3r[c] = gb3[c];
        // build initial X (transposed)
#pragma unroll
        for (int c = 0; c < 8; c++)  S.X[c * 64 + rown] = x0[c];
#pragma unroll
        for (int j = 0; j < 32; j++) S.X[(8 + j) * 64 + rown] = x0[8 + j];
#pragma unroll
        for (int q = 0; q < 8; q++)  S.X[(40 + q) * 64 + rown] = x0[40 + q];
        u0 = useq[gr * T * 2 + 0];
        u1 = useq[gr * T * 2 + 1];
        S.X[48 * 64 + rown] = u0;
        S.X[49 * 64 + rown] = u1;
    }
    __syncthreads();

#pragma unroll 1
    for (int t = 0; t < T; t++) {
        if (own) {   // y_t = xG (pre-update)
            float* op = out + (gr * T + t) * 8;
            *(float4*)(op)     = make_float4(xG[0], xG[1], xG[2], xG[3]);
            *(float4*)(op + 4) = make_float4(xG[4], xG[5], xG[6], xG[7]);
        }

#pragma unroll 1
        for (int s = 0; s < 4; s++) {
            dense_tanh<50>(S.X,  S.W1, bb1, S.H1, lam, j0);
            __syncthreads();
            dense_tanh<64>(S.H1, S.W2, bb2, S.H2, lam, j0);
            __syncthreads();

            // ---- layer 3 + RK4 epilogue on owner lanes ----
            if (own) {
                ull c3[4];
                c3[0] = 0ull; c3[1] = 0ull; c3[2] = 0ull; c3[3] = 0ull;
                const float* h2 = S.H2 + rown;
#pragma unroll 4
                for (int k = 0; k < 64; k++) {
                    const float xv = h2[k * 64];
                    ull xd; PACK2(xd, xv, xv);
                    const ulonglong2 wa = *(const ulonglong2*)(S.W3 + k * 8);
                    const ulonglong2 wb = *(const ulonglong2*)(S.W3 + k * 8 + 4);
                    FMA2(c3[0], xd, wa.x, c3[0]);
                    FMA2(c3[1], xd, wa.y, c3[1]);
                    FMA2(c3[2], xd, wb.x, c3[2]);
                    FMA2(c3[3], xd, wb.y, c3[3]);
                }
                float fnn[8];
                UNPACK2(fnn[0], fnn[1], c3[0]);
                UNPACK2(fnn[2], fnn[3], c3[1]);
                UNPACK2(fnn[4], fnn[5], c3[2]);
                UNPACK2(fnn[6], fnn[7], c3[3]);
#pragma unroll
                for (int c = 0; c < 8; c++) fnn[c] += b3r[c];

                float g[8];
                fg_eval((s == 0) ? xG : xcur, u0, u1, g);
                float kv[8];
#pragma unroll
                for (int c = 0; c < 8; c++) kv[c] = g[c] + fnn[c];

                if (s == 0) {
#pragma unroll
                    for (int c = 0; c < 8; c++) {
                        kacc[c] = kv[c];
                        xcur[c] = xG[c] + 0.005f * kv[c];
                    }
                    // zi (midpoints) -> X[8..39]
#pragma unroll
                    for (int m = 0; m < 4; m++) {
                        const float* qa = qrow + ((t + m) & 3) * 8;
                        const float* qb = qrow + ((t + m + 1) & 3) * 8;
#pragma unroll
                        for (int c = 0; c < 8; c++) {
                            const float nb = (m < 3) ? qb[c] : xG[c];
                            S.X[(8 + m * 8 + c) * 64 + rown] = 0.5f * (qa[c] + nb);
                        }
                    }
                } else if (s == 1) {
#pragma unroll
                    for (int c = 0; c < 8; c++) {
                        kacc[c] += 2.0f * kv[c];
                        xcur[c] = xG[c] + 0.005f * kv[c];
                    }
                } else if (s == 2) {
#pragma unroll
                    for (int c = 0; c < 8; c++) {
                        kacc[c] += 2.0f * kv[c];
                        xcur[c] = xG[c] + 0.01f * kv[c];
                    }
                    // zs = [ypseq[1:4], xG] -> X[8..39]
#pragma unroll
                    for (int m = 0; m < 4; m++) {
                        const float* qb = qrow + ((t + m + 1) & 3) * 8;
#pragma unroll
                        for (int c = 0; c < 8; c++) {
                            const float z = (m < 3) ? qb[c] : xG[c];
                            S.X[(8 + m * 8 + c) * 64 + rown] = z;
                        }
                    }
                } else {
#pragma unroll
                    for (int c = 0; c < 8; c++) kacc[c] += kv[c];
                    float xnew[8];
#pragma unroll
                    for (int c = 0; c < 8; c++)
                        xnew[c] = xG[c] + (0.01f / 6.0f) * kacc[c];
                    // queue: oldest slot <- xG_old
                    {
                        float* qo = qrow + (t & 3) * 8;
#pragma unroll
                        for (int c = 0; c < 8; c++) qo[c] = xG[c];
                    }
                    // ypseq_{t+1} -> X[8..39]
#pragma unroll
                    for (int m = 0; m < 4; m++) {
                        const float* qn = qrow + ((t + 1 + m) & 3) * 8;
#pragma unroll
                        for (int c = 0; c < 8; c++)
                            S.X[(8 + m * 8 + c) * 64 + rown] = qn[c];
                    }
                    // upseq shift + new u
#pragma unroll
                    for (int q = 0; q < 6; q++) up[q] = up[q + 2];
                    up[6] = u0; up[7] = u1;
#pragma unroll
                    for (int q = 0; q < 8; q++)
                        S.X[(40 + q) * 64 + rown] = up[q];
                    if (t + 1 < T) {
                        u0 = useq[(gr * T + t + 1) * 2 + 0];
                        u1 = useq[(gr * T + t + 1) * 2 + 1];
                    }
                    S.X[48 * 64 + rown] = u0;
                    S.X[49 * 64 + rown] = u1;
#pragma unroll
                    for (int c = 0; c < 8; c++) xG[c] = xnew[c];
                }
                // substep x -> X[0..7]
                const float* xw = (s == 3) ? xG : xcur;
#pragma unroll
                for (int c = 0; c < 8; c++)
                    S.X[c * 64 + rown] = xw[c];
            }
            __syncthreads();
        }
    }
}

// ---------------------------------------------------------------------------
extern "C" void kernel_launch(void* const* d_in, const int* in_sizes, int n_in,
                              void* d_out, int out_size) {
    const float* useq = (const float*)d_in[0];
    const float* xGz0 = (const float*)d_in[1];
    const float* W1   = (const float*)d_in[2];
    const float* b1   = (const float*)d_in[3];
    const float* W2   = (const float*)d_in[4];
    const float* b2   = (const float*)d_in[5];
    const float* W3   = (const float*)d_in[6];
    const float* b3   = (const float*)d_in[7];
    float* out = (float*)d_out;

    const int B = in_sizes[1] / 48;
    const int T = in_sizes[0] / (B * 2);

    const int smem = (int)sizeof(Smem);
    cudaFuncSetAttribute(cstr_flash_kernel,
                         cudaFuncAttributeMaxDynamicSharedMemorySize, smem);
    cstr_flash_kernel<<<B / BC, NT, smem>>>(useq, xGz0, W1, b1, W2, b2, W3, b3,
                                            out, T);
}

// round 12
// speedup vs baseline: 1.5476x; 1.2625x over previous
#include <cuda_runtime.h>
#include <math.h>
#include <cstdint>

#define NT 256
#define BC 64
typedef unsigned long long ull;

#define FMA2(d, a, b, c) \
    asm("fma.rn.f32x2 %0, %1, %2, %3;" : "=l"(d) : "l"(a), "l"(b), "l"(c))
#define PACK2(d, lo, hi) \
    asm("mov.b64 %0, {%1, %2};" : "=l"(d) : "f"(lo), "f"(hi))
#define UNPACK2(lo, hi, v) \
    asm("mov.b64 {%0, %1}, %2;" : "=f"(lo), "=f"(hi) : "l"(v))

__device__ __forceinline__ float tanh_fast(float x) {
    float y;
    asm("tanh.approx.f32 %0, %1;" : "=f"(y) : "f"(x));
    return y;
}

// ---------------------------------------------------------------------------
// X/H1 transposed [k][row] (pitch 64). Part: 64 planes (w*8+j) of 66 floats,
// plane p, row r at float p*66 + r  ({r0,r1} ull stores are conflict-free).
// All sizes multiples of 4 floats -> 16B aligned.
// ---------------------------------------------------------------------------
struct __align__(16) Smem {
    float X[52 * 64];      // MLP input, transposed [k][row]
    float H1[64 * 64];     // hidden1 transposed [j][row]
    float Part[64 * 66];   // L3 partials: plane (w*8+j), float index = row
    float W1[50 * 64];     // [k][j]
    float W2[64 * 64];     // [k][j]
    float W3d[64 * 16];    // W3 duplicated pairs: [k][j] -> {w,w}
    float Q[64 * 33];      // ypseq circular queue per row
};

// ---------------------------------------------------------------------------
// Grey-box CSTR+flash RHS (scaled), fp32, matches reference _fg.
// ---------------------------------------------------------------------------
__device__ __forceinline__ void fg_eval(const float* x, float u0f, float u1f,
                                        float* g) {
    const float Hr  = 0.3f * x[0] + 0.7f;
    const float CAr = 0.2f * x[1] + 0.5f;
    const float CBr = 0.2f * x[2] + 0.5f;
    const float Tr  = 5.0f * x[3] + 310.0f;
    const float Hb  = 0.3f * x[4] + 0.7f;
    const float CAb = 0.2f * x[5] + 0.5f;
    const float CBb = 0.2f * x[6] + 0.5f;
    const float Tb  = 5.0f * x[7] + 310.0f;
    const float Fu  = 0.1f  * u0f + 1.0f;
    const float Du  = 0.05f * u1f + 0.5f;

    const float den = 3.5f * CAb + 1.1f * CBb;
    const float CAd = 3.5f * CAb / den;
    const float CBd = 1.1f * CBb / den;
    const float Fr  = sqrtf(Hr);
    const float Fb  = sqrtf(Hb);
    const float k1c = 20000.0f * expf(-3000.0f / Tr);
    const float r1  = k1c * CAr;
    const float rHr = 1.0f / Hr;
    const float rHb = 1.0f / Hb;

    g[0] = (Fu + Du - Fr) * (1.0f / 0.3f);
    g[1] = ((Fu * (1.0f - CAr) + Du * (CAd - CAr)) * rHr - r1) * (1.0f / 0.2f);
    g[2] = ((-Fu * CBr + Du * (CBd - CBr)) * rHr + r1) * (1.0f / 0.2f);
    g[3] = ((Fu * (320.0f - Tr) + Du * (310.0f - Tr)) * rHr
            - (200.0f / 15.0f) * rHr + r1 * (10.0f / 15.0f)) * (1.0f / 5.0f);
    g[4] = (Fr - Fb - Du) * (1.0f / 0.3f);
    g[5] = ((Fr * (CAr - CAb) + Du * (CAb - CAd)) * rHb) * (1.0f / 0.2f);
    g[6] = ((Fr * (CBr - CBb) + Du * (CBb - CBd)) * rHb) * (1.0f / 0.2f);
    g[7] = (Fr * (Tr - Tb) * rHb + (200.0f / 15.0f) * rHb) * (1.0f / 5.0f);
}

// ---------------------------------------------------------------------------
// Dense layer 1 + tanh -> H1 (smem). Warp = 64 rows x 8 cols; thread = rows
// {2lam, 2lam+1} x cols [j0, j0+8).
// ---------------------------------------------------------------------------
__device__ __forceinline__ void dense1(const float* __restrict__ Xs,
                                       const float* __restrict__ Ws,
                                       const ull* __restrict__ bb,
                                       float* __restrict__ Ys,
                                       int lam, int j0) {
    ull a0[4], a1[4];
#pragma unroll
    for (int p = 0; p < 4; p++) { a0[p] = bb[p]; a1[p] = bb[p]; }

    const float* xs = Xs + 2 * lam;
    const float* wj = Ws + j0;
#pragma unroll 5
    for (int k = 0; k < 50; k++) {
        const float2 xv = *(const float2*)(xs + k * 64);
        ull xa, xb;
        PACK2(xa, xv.x, xv.x);
        PACK2(xb, xv.y, xv.y);
        const float* w = wj + k * 64;
        const ulonglong2 wA = *(const ulonglong2*)(w);
        const ulonglong2 wB = *(const ulonglong2*)(w + 4);
        FMA2(a0[0], xa, wA.x, a0[0]);  FMA2(a1[0], xb, wA.x, a1[0]);
        FMA2(a0[1], xa, wA.y, a0[1]);  FMA2(a1[1], xb, wA.y, a1[1]);
        FMA2(a0[2], xa, wB.x, a0[2]);  FMA2(a1[2], xb, wB.x, a1[2]);
        FMA2(a0[3], xa, wB.y, a0[3]);  FMA2(a1[3], xb, wB.y, a1[3]);
    }
    float* ys = Ys + 2 * lam;
#pragma unroll
    for (int p = 0; p < 4; p++) {
        float f00, f01, f10, f11;
        UNPACK2(f00, f01, a0[p]);
        UNPACK2(f10, f11, a1[p]);
        const float t00 = tanh_fast(f00), t10 = tanh_fast(f10);
        const float t01 = tanh_fast(f01), t11 = tanh_fast(f11);
        *(float2*)(ys + (j0 + 2 * p) * 64)     = make_float2(t00, t10);
        *(float2*)(ys + (j0 + 2 * p + 1) * 64) = make_float2(t01, t11);
    }
}

// ---------------------------------------------------------------------------
// Persistent kernel: CTA = 64 rows, 256 threads (8 warps, 2/SMSP).
// dense1 -> bar -> dense2(+tanh, regs) + fused L3 partials -> bar ->
// owner reduce + fg + RK4 + X rebuild -> bar.
// ---------------------------------------------------------------------------
__global__ void __launch_bounds__(NT, 1)
cstr_flash_kernel(const float* __restrict__ useq, const float* __restrict__ xGz0,
                  const float* __restrict__ gW1, const float* __restrict__ gb1,
                  const float* __restrict__ gW2, const float* __restrict__ gb2,
                  const float* __restrict__ gW3, const float* __restrict__ gb3,
                  float* __restrict__ out, int T) {
    extern __shared__ char smem_raw[];
    Smem& S = *reinterpret_cast<Smem*>(smem_raw);

    const int tid = threadIdx.x;
    const int wid = tid >> 5;
    const int lam = tid & 31;
    const int j0  = wid * 8;

    // weights
    for (int i = tid; i < 50 * 64; i += NT) S.W1[i] = gW1[i];
    for (int i = tid; i < 64 * 64; i += NT) S.W2[i] = gW2[i];
    for (int i = tid; i < 64 * 8; i += NT) {         // duplicated W3
        const float w = gW3[i];
        S.W3d[2 * i] = w; S.W3d[2 * i + 1] = w;
    }

    // bias pairs for this warp's 8 columns
    ull bb1[4], bb2[4];
#pragma unroll
    for (int p = 0; p < 4; p++) {
        PACK2(bb1[p], gb1[j0 + 2 * p], gb1[j0 + 2 * p + 1]);
        PACK2(bb2[p], gb2[j0 + 2 * p], gb2[j0 + 2 * p + 1]);
    }

    // owner mapping: lanes 0..7 of each warp own rows wid*8 + lam
    const bool own  = (lam < 8);
    const int  rown = wid * 8 + (lam & 7);
    const long gr   = (long)blockIdx.x * BC + rown;
    float* qrow = S.Q + rown * 33;

    float xG[8], xcur[8], kacc[8], up[8], b3r[8];
    float u0 = 0.f, u1 = 0.f;
#pragma unroll
    for (int c = 0; c < 8; c++) { xG[c] = 0.f; xcur[c] = 0.f; kacc[c] = 0.f; up[c] = 0.f; b3r[c] = 0.f; }

    if (own) {
        const float* x0 = xGz0 + gr * 48;
#pragma unroll
        for (int c = 0; c < 8; c++) xG[c] = x0[c];
#pragma unroll
        for (int m = 0; m < 4; m++)
#pragma unroll
            for (int c = 0; c < 8; c++) qrow[m * 8 + c] = x0[8 + 8 * m + c];
#pragma unroll
        for (int q = 0; q < 8; q++) up[q] = x0[40 + q];
#pragma unroll
        for (int c = 0; c < 8; c++) b3r[c] = gb3[c];
        // initial X (transposed)
#pragma unroll
        for (int c = 0; c < 8; c++)  S.X[c * 64 + rown] = x0[c];
#pragma unroll
        for (int j = 0; j < 32; j++) S.X[(8 + j) * 64 + rown] = x0[8 + j];
#pragma unroll
        for (int q = 0; q < 8; q++)  S.X[(40 + q) * 64 + rown] = x0[40 + q];
        u0 = useq[gr * T * 2 + 0];
        u1 = useq[gr * T * 2 + 1];
        S.X[48 * 64 + rown] = u0;
        S.X[49 * 64 + rown] = u1;
    }
    __syncthreads();

#pragma unroll 1
    for (int t = 0; t < T; t++) {
        if (own) {   // y_t = xG (pre-update)
            float* op = out + (gr * T + t) * 8;
            *(float4*)(op)     = make_float4(xG[0], xG[1], xG[2], xG[3]);
            *(float4*)(op + 4) = make_float4(xG[4], xG[5], xG[6], xG[7]);
        }

#pragma unroll 1
        for (int s = 0; s < 4; s++) {
            dense1(S.X, S.W1, bb1, S.H1, lam, j0);
            __syncthreads();

            // ---- dense2 (H1 -> regs) ----
            ull a0[4], a1[4];
#pragma unroll
            for (int p = 0; p < 4; p++) { a0[p] = bb2[p]; a1[p] = bb2[p]; }
            {
                const float* xs = S.H1 + 2 * lam;
                const float* wj = S.W2 + j0;
#pragma unroll 4
                for (int k = 0; k < 64; k++) {
                    const float2 xv = *(const float2*)(xs + k * 64);
                    ull xa, xb;
                    PACK2(xa, xv.x, xv.x);
                    PACK2(xb, xv.y, xv.y);
                    const float* w = wj + k * 64;
                    const ulonglong2 wA = *(const ulonglong2*)(w);
                    const ulonglong2 wB = *(const ulonglong2*)(w + 4);
                    FMA2(a0[0], xa, wA.x, a0[0]);  FMA2(a1[0], xb, wA.x, a1[0]);
                    FMA2(a0[1], xa, wA.y, a0[1]);  FMA2(a1[1], xb, wA.y, a1[1]);
                    FMA2(a0[2], xa, wB.x, a0[2]);  FMA2(a1[2], xb, wB.x, a1[2]);
                    FMA2(a0[3], xa, wB.y, a0[3]);  FMA2(a1[3], xb, wB.y, a1[3]);
                }
            }
            // tanh -> t0/t1 scalars (H2 slice in regs)
            float t0[8], t1[8];
#pragma unroll
            for (int p = 0; p < 4; p++) {
                float f00, f01, f10, f11;
                UNPACK2(f00, f01, a0[p]);
                UNPACK2(f10, f11, a1[p]);
                t0[2 * p]     = tanh_fast(f00);
                t0[2 * p + 1] = tanh_fast(f01);
                t1[2 * p]     = tanh_fast(f10);
                t1[2 * p + 1] = tanh_fast(f11);
            }

            // ---- fused L3 partials: p3[j] = {P_r0[j], P_r1[j]} ----
            ull p3[8];
#pragma unroll
            for (int j = 0; j < 8; j++) p3[j] = 0ull;
#pragma unroll
            for (int i = 0; i < 8; i++) {
                ull xp;
                PACK2(xp, t0[i], t1[i]);
                const ull* wd = (const ull*)(S.W3d) + (j0 + i) * 8;
                const ulonglong2 w0 = *(const ulonglong2*)(wd);
                const ulonglong2 w1 = *(const ulonglong2*)(wd + 2);
                const ulonglong2 w2 = *(const ulonglong2*)(wd + 4);
                const ulonglong2 w3 = *(const ulonglong2*)(wd + 6);
                FMA2(p3[0], xp, w0.x, p3[0]);
                FMA2(p3[1], xp, w0.y, p3[1]);
                FMA2(p3[2], xp, w1.x, p3[2]);
                FMA2(p3[3], xp, w1.y, p3[3]);
                FMA2(p3[4], xp, w2.x, p3[4]);
                FMA2(p3[5], xp, w2.y, p3[5]);
                FMA2(p3[6], xp, w3.x, p3[6]);
                FMA2(p3[7], xp, w3.y, p3[7]);
            }
            // store partials: plane (wid*8+j), rows {2lam,2lam+1} as one ull
#pragma unroll
            for (int j = 0; j < 8; j++)
                *(ull*)(S.Part + (wid * 8 + j) * 66 + 2 * lam) = p3[j];
            __syncthreads();

            // ---- owner: reduce partials + fg + RK4 + X rebuild ----
            if (own) {
                float fnn[8];
#pragma unroll
                for (int j = 0; j < 8; j++) fnn[j] = b3r[j];
#pragma unroll
                for (int w = 0; w < 8; w++)
#pragma unroll
                    for (int j = 0; j < 8; j++)
                        fnn[j] += S.Part[(w * 8 + j) * 66 + rown];

                float g[8];
                fg_eval((s == 0) ? xG : xcur, u0, u1, g);
                float kv[8];
#pragma unroll
                for (int c = 0; c < 8; c++) kv[c] = g[c] + fnn[c];

                if (s == 0) {
#pragma unroll
                    for (int c = 0; c < 8; c++) {
                        kacc[c] = kv[c];
                        xcur[c] = xG[c] + 0.005f * kv[c];
                    }
                    // zi (midpoints) -> X[8..39]
#pragma unroll
                    for (int m = 0; m < 4; m++) {
                        const float* qa = qrow + ((t + m) & 3) * 8;
                        const float* qb = qrow + ((t + m + 1) & 3) * 8;
#pragma unroll
                        for (int c = 0; c < 8; c++) {
                            const float nb = (m < 3) ? qb[c] : xG[c];
                            S.X[(8 + m * 8 + c) * 64 + rown] = 0.5f * (qa[c] + nb);
                        }
                    }
                } else if (s == 1) {
#pragma unroll
                    for (int c = 0; c < 8; c++) {
                        kacc[c] += 2.0f * kv[c];
                        xcur[c] = xG[c] + 0.005f * kv[c];
                    }
                } else if (s == 2) {
#pragma unroll
                    for (int c = 0; c < 8; c++) {
                        kacc[c] += 2.0f * kv[c];
                        xcur[c] = xG[c] + 0.01f * kv[c];
                    }
                    // zs = [ypseq[1:4], xG] -> X[8..39]
#pragma unroll
                    for (int m = 0; m < 4; m++) {
                        const float* qb = qrow + ((t + m + 1) & 3) * 8;
#pragma unroll
                        for (int c = 0; c < 8; c++) {
                            const float z = (m < 3) ? qb[c] : xG[c];
                            S.X[(8 + m * 8 + c) * 64 + rown] = z;
                        }
                    }
                } else {
#pragma unroll
                    for (int c = 0; c < 8; c++) kacc[c] += kv[c];
                    float xnew[8];
#pragma unroll
                    for (int c = 0; c < 8; c++)
                        xnew[c] = xG[c] + (0.01f / 6.0f) * kacc[c];
                    // queue: oldest slot <- xG_old
                    {
                        float* qo = qrow + (t & 3) * 8;
#pragma unroll
                        for (int c = 0; c < 8; c++) qo[c] = xG[c];
                    }
                    // ypseq_{t+1} -> X[8..39]
#pragma unroll
                    for (int m = 0; m < 4; m++) {
                        const float* qn = qrow + ((t + 1 + m) & 3) * 8;
#pragma unroll
                        for (int c = 0; c < 8; c++)
                            S.X[(8 + m * 8 + c) * 64 + rown] = qn[c];
                    }
                    // upseq shift + new u
#pragma unroll
                    for (int q = 0; q < 6; q++) up[q] = up[q + 2];
                    up[6] = u0; up[7] = u1;
#pragma unroll
                    for (int q = 0; q < 8; q++)
                        S.X[(40 + q) * 64 + rown] = up[q];
                    if (t + 1 < T) {
                        u0 = useq[(gr * T + t + 1) * 2 + 0];
                        u1 = useq[(gr * T + t + 1) * 2 + 1];
                    }
                    S.X[48 * 64 + rown] = u0;
                    S.X[49 * 64 + rown] = u1;
#pragma unroll
                    for (int c = 0; c < 8; c++) xG[c] = xnew[c];
                }
                // substep x -> X[0..7]
                const float* xw = (s == 3) ? xG : xcur;
#pragma unroll
                for (int c = 0; c < 8; c++)
                    S.X[c * 64 + rown] = xw[c];
            }
            __syncthreads();
        }
    }
}

// ---------------------------------------------------------------------------
extern "C" void kernel_launch(void* const* d_in, const int* in_sizes, int n_in,
                              void* d_out, int out_size) {
    const float* useq = (const float*)d_in[0];
    const float* xGz0 = (const float*)d_in[1];
    const float* W1   = (const float*)d_in[2];
    const float* b1   = (const float*)d_in[3];
    const float* W2   = (const float*)d_in[4];
    const float* b2   = (const float*)d_in[5];
    const float* W3   = (const float*)d_in[6];
    const float* b3   = (const float*)d_in[7];
    float* out = (float*)d_out;

    const int B = in_sizes[1] / 48;
    const int T = in_sizes[0] / (B * 2);

    const int smem = (int)sizeof(Smem);
    cudaFuncSetAttribute(cstr_flash_kernel,
                         cudaFuncAttributeMaxDynamicSharedMemorySize, smem);
    cstr_flash_kernel<<<B / BC, NT, smem>>>(useq, xGz0, W1, b1, W2, b2, W3, b3,
                                            out, T);
}

// round 13
// speedup vs baseline: 1.6827x; 1.0873x over previous
#include <cuda_runtime.h>
#include <math.h>
#include <cstdint>

#define NT 256
#define BC 64
typedef unsigned long long ull;

#define FMA2(d, a, b, c) \
    asm("fma.rn.f32x2 %0, %1, %2, %3;" : "=l"(d) : "l"(a), "l"(b), "l"(c))
#define PACK2(d, lo, hi) \
    asm("mov.b64 %0, {%1, %2};" : "=l"(d) : "f"(lo), "f"(hi))
#define UNPACK2(lo, hi, v) \
    asm("mov.b64 {%0, %1}, %2;" : "=f"(lo), "=f"(hi) : "l"(v))

// pack two f32 -> f16x2, tanh both halves in ONE MUFU op
__device__ __forceinline__ uint32_t tanh2_f16(float lo, float hi) {
    uint32_t h;
    asm("cvt.rn.f16x2.f32 %0, %1, %2;" : "=r"(h) : "f"(hi), "f"(lo));
    asm("tanh.approx.f16x2 %0, %0;" : "+r"(h));
    return h;
}
__device__ __forceinline__ void unpack_h2(float& lo, float& hi, uint32_t h) {
    asm("{ .reg .f16 l, u; mov.b32 {l, u}, %2;"
        " cvt.f32.f16 %0, l; cvt.f32.f16 %1, u; }"
        : "=f"(lo), "=f"(hi) : "r"(h));
}
__device__ __forceinline__ float rcp_fast(float x) {
    float y; asm("rcp.approx.f32 %0, %1;" : "=f"(y) : "f"(x)); return y;
}
__device__ __forceinline__ float sqrt_fast(float x) {
    float y; asm("sqrt.approx.f32 %0, %1;" : "=f"(y) : "f"(x)); return y;
}

// ---------------------------------------------------------------------------
// X transposed [k][row]; H1 as f16x2 row-pairs: H1h[j*32 + lam] = {r2lam, r2lam+1}.
// Part: 64 planes of 66 floats. All sizes multiples of 4 floats.
// ---------------------------------------------------------------------------
struct __align__(16) Smem {
    float    X[52 * 64];     // MLP input, transposed [k][row]
    uint32_t H1h[64 * 32];   // hidden1, f16x2 packed row pairs
    float    Part[64 * 66];  // L3 partials: plane (w*8+j), float index = row
    float    W1[50 * 64];    // [k][j]
    float    W2[64 * 64];    // [k][j]
    float    W3d[64 * 16];   // W3 duplicated pairs
    float    Q[64 * 33];     // ypseq circular queue per row
};

// ---------------------------------------------------------------------------
// Grey-box CSTR+flash RHS (scaled); approx rcp/sqrt/exp (err ~2e-7).
// ---------------------------------------------------------------------------
__device__ __forceinline__ void fg_eval(const float* x, float u0f, float u1f,
                                        float* g) {
    const float Hr  = 0.3f * x[0] + 0.7f;
    const float CAr = 0.2f * x[1] + 0.5f;
    const float CBr = 0.2f * x[2] + 0.5f;
    const float Tr  = 5.0f * x[3] + 310.0f;
    const float Hb  = 0.3f * x[4] + 0.7f;
    const float CAb = 0.2f * x[5] + 0.5f;
    const float CBb = 0.2f * x[6] + 0.5f;
    const float Tb  = 5.0f * x[7] + 310.0f;
    const float Fu  = 0.1f  * u0f + 1.0f;
    const float Du  = 0.05f * u1f + 0.5f;

    const float rden = rcp_fast(3.5f * CAb + 1.1f * CBb);
    const float CAd = 3.5f * CAb * rden;
    const float CBd = 1.1f * CBb * rden;
    const float Fr  = sqrt_fast(Hr);
    const float Fb  = sqrt_fast(Hb);
    const float k1c = 20000.0f * __expf(-3000.0f * rcp_fast(Tr));
    const float r1  = k1c * CAr;
    const float rHr = rcp_fast(Hr);
    const float rHb = rcp_fast(Hb);

    g[0] = (Fu + Du - Fr) * (1.0f / 0.3f);
    g[1] = ((Fu * (1.0f - CAr) + Du * (CAd - CAr)) * rHr - r1) * (1.0f / 0.2f);
    g[2] = ((-Fu * CBr + Du * (CBd - CBr)) * rHr + r1) * (1.0f / 0.2f);
    g[3] = ((Fu * (320.0f - Tr) + Du * (310.0f - Tr)) * rHr
            - (200.0f / 15.0f) * rHr + r1 * (10.0f / 15.0f)) * (1.0f / 5.0f);
    g[4] = (Fr - Fb - Du) * (1.0f / 0.3f);
    g[5] = ((Fr * (CAr - CAb) + Du * (CAb - CAd)) * rHb) * (1.0f / 0.2f);
    g[6] = ((Fr * (CBr - CBb) + Du * (CBb - CBd)) * rHb) * (1.0f / 0.2f);
    g[7] = (Fr * (Tr - Tb) * rHb + (200.0f / 15.0f) * rHb) * (1.0f / 5.0f);
}

// ---------------------------------------------------------------------------
// Persistent kernel: CTA = 64 rows, 256 threads (8 warps, 2/SMSP).
// dense1 (X f32 -> H1 f16x2) -> bar -> dense2 (H1 f16x2 -> regs) + fused L3
// partials -> bar -> owner reduce + fg + RK4 + X rebuild -> bar.
// ---------------------------------------------------------------------------
__global__ void __launch_bounds__(NT, 1)
cstr_flash_kernel(const float* __restrict__ useq, const float* __restrict__ xGz0,
                  const float* __restrict__ gW1, const float* __restrict__ gb1,
                  const float* __restrict__ gW2, const float* __restrict__ gb2,
                  const float* __restrict__ gW3, const float* __restrict__ gb3,
                  float* __restrict__ out, int T) {
    extern __shared__ char smem_raw[];
    Smem& S = *reinterpret_cast<Smem*>(smem_raw);

    const int tid = threadIdx.x;
    const int wid = tid >> 5;
    const int lam = tid & 31;
    const int j0  = wid * 8;

    // weights
    for (int i = tid; i < 50 * 64; i += NT) S.W1[i] = gW1[i];
    for (int i = tid; i < 64 * 64; i += NT) S.W2[i] = gW2[i];
    for (int i = tid; i < 64 * 8; i += NT) {
        const float w = gW3[i];
        S.W3d[2 * i] = w; S.W3d[2 * i + 1] = w;
    }

    // bias pairs for this warp's 8 columns
    ull bb1[4], bb2[4];
#pragma unroll
    for (int p = 0; p < 4; p++) {
        PACK2(bb1[p], gb1[j0 + 2 * p], gb1[j0 + 2 * p + 1]);
        PACK2(bb2[p], gb2[j0 + 2 * p], gb2[j0 + 2 * p + 1]);
    }

    // owner mapping: lanes 0..7 of each warp own rows wid*8 + lam
    const bool own  = (lam < 8);
    const int  rown = wid * 8 + (lam & 7);
    const long gr   = (long)blockIdx.x * BC + rown;
    float* qrow = S.Q + rown * 33;

    float xG[8], xcur[8], kacc[8], up[8], b3r[8];
    float u0 = 0.f, u1 = 0.f;
#pragma unroll
    for (int c = 0; c < 8; c++) { xG[c] = 0.f; xcur[c] = 0.f; kacc[c] = 0.f; up[c] = 0.f; b3r[c] = 0.f; }

    if (own) {
        const float* x0 = xGz0 + gr * 48;
#pragma unroll
        for (int c = 0; c < 8; c++) xG[c] = x0[c];
#pragma unroll
        for (int m = 0; m < 4; m++)
#pragma unroll
            for (int c = 0; c < 8; c++) qrow[m * 8 + c] = x0[8 + 8 * m + c];
#pragma unroll
        for (int q = 0; q < 8; q++) up[q] = x0[40 + q];
#pragma unroll
        for (int c = 0; c < 8; c++) b3r[c] = gb3[c];
        // initial X (transposed)
#pragma unroll
        for (int c = 0; c < 8; c++)  S.X[c * 64 + rown] = x0[c];
#pragma unroll
        for (int j = 0; j < 32; j++) S.X[(8 + j) * 64 + rown] = x0[8 + j];
#pragma unroll
        for (int q = 0; q < 8; q++)  S.X[(40 + q) * 64 + rown] = x0[40 + q];
        u0 = useq[gr * T * 2 + 0];
        u1 = useq[gr * T * 2 + 1];
        S.X[48 * 64 + rown] = u0;
        S.X[49 * 64 + rown] = u1;
    }
    __syncthreads();

#pragma unroll 1
    for (int t = 0; t < T; t++) {
        if (own) {   // y_t = xG (pre-update)
            float* op = out + (gr * T + t) * 8;
            *(float4*)(op)     = make_float4(xG[0], xG[1], xG[2], xG[3]);
            *(float4*)(op + 4) = make_float4(xG[4], xG[5], xG[6], xG[7]);
        }

#pragma unroll 1
        for (int s = 0; s < 4; s++) {
            // ---- dense1: X (f32) -> H1h (f16x2) ----
            {
                ull a0[4], a1[4];
#pragma unroll
                for (int p = 0; p < 4; p++) { a0[p] = bb1[p]; a1[p] = bb1[p]; }
                const float* xs = S.X + 2 * lam;
                const float* wj = S.W1 + j0;
#pragma unroll 10
                for (int k = 0; k < 50; k++) {
                    const float2 xv = *(const float2*)(xs + k * 64);
                    ull xa, xb;
                    PACK2(xa, xv.x, xv.x);
                    PACK2(xb, xv.y, xv.y);
                    const float* w = wj + k * 64;
                    const ulonglong2 wA = *(const ulonglong2*)(w);
                    const ulonglong2 wB = *(const ulonglong2*)(w + 4);
                    FMA2(a0[0], xa, wA.x, a0[0]);  FMA2(a1[0], xb, wA.x, a1[0]);
                    FMA2(a0[1], xa, wA.y, a0[1]);  FMA2(a1[1], xb, wA.y, a1[1]);
                    FMA2(a0[2], xa, wB.x, a0[2]);  FMA2(a1[2], xb, wB.x, a1[2]);
                    FMA2(a0[3], xa, wB.y, a0[3]);  FMA2(a1[3], xb, wB.y, a1[3]);
                }
#pragma unroll
                for (int p = 0; p < 4; p++) {
                    float f00, f01, f10, f11;
                    UNPACK2(f00, f01, a0[p]);   // row 2lam, cols 2p, 2p+1
                    UNPACK2(f10, f11, a1[p]);   // row 2lam+1
                    S.H1h[(j0 + 2 * p) * 32 + lam]     = tanh2_f16(f00, f10);
                    S.H1h[(j0 + 2 * p + 1) * 32 + lam] = tanh2_f16(f01, f11);
                }
            }
            __syncthreads();

            // ---- dense2 (H1h -> regs) ----
            ull a0[4], a1[4];
#pragma unroll
            for (int p = 0; p < 4; p++) { a0[p] = bb2[p]; a1[p] = bb2[p]; }
            {
                const uint32_t* xs = S.H1h + lam;
                const float* wj = S.W2 + j0;
#pragma unroll 8
                for (int k = 0; k < 64; k++) {
                    float x0f, x1f;
                    unpack_h2(x0f, x1f, xs[k * 32]);
                    ull xa, xb;
                    PACK2(xa, x0f, x0f);
                    PACK2(xb, x1f, x1f);
                    const float* w = wj + k * 64;
                    const ulonglong2 wA = *(const ulonglong2*)(w);
                    const ulonglong2 wB = *(const ulonglong2*)(w + 4);
                    FMA2(a0[0], xa, wA.x, a0[0]);  FMA2(a1[0], xb, wA.x, a1[0]);
                    FMA2(a0[1], xa, wA.y, a0[1]);  FMA2(a1[1], xb, wA.y, a1[1]);
                    FMA2(a0[2], xa, wB.x, a0[2]);  FMA2(a1[2], xb, wB.x, a1[2]);
                    FMA2(a0[3], xa, wB.y, a0[3]);  FMA2(a1[3], xb, wB.y, a1[3]);
                }
            }
            // tanh (f16x2 MUFU) -> paired {row0,row1} ulls for fused L3
            ull h2p[8];
#pragma unroll
            for (int p = 0; p < 4; p++) {
                float f00, f01, f10, f11;
                UNPACK2(f00, f01, a0[p]);
                UNPACK2(f10, f11, a1[p]);
                float t0f, t1f;
                unpack_h2(t0f, t1f, tanh2_f16(f00, f10));
                PACK2(h2p[2 * p], t0f, t1f);
                unpack_h2(t0f, t1f, tanh2_f16(f01, f11));
                PACK2(h2p[2 * p + 1], t0f, t1f);
            }

            // ---- fused L3 partials: p3[j] = {P_r0[j], P_r1[j]} ----
            ull p3[8];
#pragma unroll
            for (int j = 0; j < 8; j++) p3[j] = 0ull;
#pragma unroll
            for (int i = 0; i < 8; i++) {
                const ull xp = h2p[i];
                const ull* wd = (const ull*)(S.W3d) + (j0 + i) * 8;
                const ulonglong2 w0 = *(const ulonglong2*)(wd);
                const ulonglong2 w1 = *(const ulonglong2*)(wd + 2);
                const ulonglong2 w2 = *(const ulonglong2*)(wd + 4);
                const ulonglong2 w3 = *(const ulonglong2*)(wd + 6);
                FMA2(p3[0], xp, w0.x, p3[0]);
                FMA2(p3[1], xp, w0.y, p3[1]);
                FMA2(p3[2], xp, w1.x, p3[2]);
                FMA2(p3[3], xp, w1.y, p3[3]);
                FMA2(p3[4], xp, w2.x, p3[4]);
                FMA2(p3[5], xp, w2.y, p3[5]);
                FMA2(p3[6], xp, w3.x, p3[6]);
                FMA2(p3[7], xp, w3.y, p3[7]);
            }
#pragma unroll
            for (int j = 0; j < 8; j++)
                *(ull*)(S.Part + (wid * 8 + j) * 66 + 2 * lam) = p3[j];
            __syncthreads();

            // ---- owner: reduce partials + fg + RK4 + X rebuild ----
            if (own) {
                float fnn[8];
#pragma unroll
                for (int j = 0; j < 8; j++) fnn[j] = b3r[j];
#pragma unroll
                for (int w = 0; w < 8; w++)
#pragma unroll
                    for (int j = 0; j < 8; j++)
                        fnn[j] += S.Part[(w * 8 + j) * 66 + rown];

                float g[8];
                fg_eval((s == 0) ? xG : xcur, u0, u1, g);
                float kv[8];
#pragma unroll
                for (int c = 0; c < 8; c++) kv[c] = g[c] + fnn[c];

                if (s == 0) {
#pragma unroll
                    for (int c = 0; c < 8; c++) {
                        kacc[c] = kv[c];
                        xcur[c] = xG[c] + 0.005f * kv[c];
                    }
#pragma unroll
                    for (int m = 0; m < 4; m++) {
                        const float* qa = qrow + ((t + m) & 3) * 8;
                        const float* qb = qrow + ((t + m + 1) & 3) * 8;
#pragma unroll
                        for (int c = 0; c < 8; c++) {
                            const float nb = (m < 3) ? qb[c] : xG[c];
                            S.X[(8 + m * 8 + c) * 64 + rown] = 0.5f * (qa[c] + nb);
                        }
                    }
                } else if (s == 1) {
#pragma unroll
                    for (int c = 0; c < 8; c++) {
                        kacc[c] += 2.0f * kv[c];
                        xcur[c] = xG[c] + 0.005f * kv[c];
                    }
                } else if (s == 2) {
#pragma unroll
                    for (int c = 0; c < 8; c++) {
                        kacc[c] += 2.0f * kv[c];
                        xcur[c] = xG[c] + 0.01f * kv[c];
                    }
#pragma unroll
                    for (int m = 0; m < 4; m++) {
                        const float* qb = qrow + ((t + m + 1) & 3) * 8;
#pragma unroll
                        for (int c = 0; c < 8; c++) {
                            const float z = (m < 3) ? qb[c] : xG[c];
                            S.X[(8 + m * 8 + c) * 64 + rown] = z;
                        }
                    }
                } else {
#pragma unroll
                    for (int c = 0; c < 8; c++) kacc[c] += kv[c];
                    float xnew[8];
#pragma unroll
                    for (int c = 0; c < 8; c++)
                        xnew[c] = xG[c] + (0.01f / 6.0f) * kacc[c];
                    {
                        float* qo = qrow + (t & 3) * 8;
#pragma unroll
                        for (int c = 0; c < 8; c++) qo[c] = xG[c];
                    }
#pragma unroll
                    for (int m = 0; m < 4; m++) {
                        const float* qn = qrow + ((t + 1 + m) & 3) * 8;
#pragma unroll
                        for (int c = 0; c < 8; c++)
                            S.X[(8 + m * 8 + c) * 64 + rown] = qn[c];
                    }
#pragma unroll
                    for (int q = 0; q < 6; q++) up[q] = up[q + 2];
                    up[6] = u0; up[7] = u1;
#pragma unroll
                    for (int q = 0; q < 8; q++)
                        S.X[(40 + q) * 64 + rown] = up[q];
                    if (t + 1 < T) {
                        u0 = useq[(gr * T + t + 1) * 2 + 0];
                        u1 = useq[(gr * T + t + 1) * 2 + 1];
                    }
                    S.X[48 * 64 + rown] = u0;
                    S.X[49 * 64 + rown] = u1;
#pragma unroll
                    for (int c = 0; c < 8; c++) xG[c] = xnew[c];
                }
                const float* xw = (s == 3) ? xG : xcur;
#pragma unroll
                for (int c = 0; c < 8; c++)
                    S.X[c * 64 + rown] = xw[c];
            }
            __syncthreads();
        }
    }
}

// ---------------------------------------------------------------------------
extern "C" void kernel_launch(void* const* d_in, const int* in_sizes, int n_in,
                              void* d_out, int out_size) {
    const float* useq = (const float*)d_in[0];
    const float* xGz0 = (const float*)d_in[1];
    const float* W1   = (const float*)d_in[2];
    const float* b1   = (const float*)d_in[3];
    const float* W2   = (const float*)d_in[4];
    const float* b2   = (const float*)d_in[5];
    const float* W3   = (const float*)d_in[6];
    const float* b3   = (const float*)d_in[7];
    float* out = (float*)d_out;

    const int B = in_sizes[1] / 48;
    const int T = in_sizes[0] / (B * 2);

    const int smem = (int)sizeof(Smem);
    cudaFuncSetAttribute(cstr_flash_kernel,
                         cudaFuncAttributeMaxDynamicSharedMemorySize, smem);
    cstr_flash_kernel<<<B / BC, NT, smem>>>(useq, xGz0, W1, b1, W2, b2, W3, b3,
                                            out, T);
}